// round 1
// baseline (speedup 1.0000x reference)
#include <cuda_runtime.h>
#include <cstdint>

// ---------------------------------------------------------------------------
// RecurrentGCN (GCLSTM cell + MLP head), full fp32, packed f32x2 FMA pipeline.
//
// Inputs (metadata order):
//  0 x[N,16] 1 edge_index(2E,i32, unused) 2 edge_weight(E, unused)
//  3 h[N,128] 4 c[N,128]
//  5..8  W_i,W_f,W_c,W_o            [16,128]
//  9..12 conv_i_w..conv_o_w         [128,128]
// 13..16 conv_i_b..conv_o_b         [128]
// 17..19 w_ci,w_cf,w_co             [1,128]
// 20..23 b_i,b_f,b_c,b_o            [1,128]
// 24 mlp_w1[128,64] 25 mlp_b1[64] 26 mlp_w2[64,64] 27 mlp_b2[64]
// 28 mlp_w3[64,1]   29 mlp_b3[1]
//
// Output d_out: out[N] | h_new[N,128] | c_new[N,128]
// ---------------------------------------------------------------------------

typedef unsigned long long ull;

// Packed gate weights: B[k][g*128+j], k<16 -> W_g, k>=16 -> conv_g_w[k-16].
__device__ float g_B[144 * 512];
__device__ float g_bias[512];   // conv_g_b[j] + b_g[j]

__device__ __forceinline__ ull pack2(float x, float y) {
    ull r; asm("mov.b64 %0, {%1, %2};" : "=l"(r) : "f"(x), "f"(y)); return r;
}
__device__ __forceinline__ void unpack2(ull v, float& x, float& y) {
    asm("mov.b64 {%0, %1}, %2;" : "=f"(x), "=f"(y) : "l"(v));
}
// d = a * b + d  (packed 2 x fp32)
__device__ __forceinline__ void fma2(ull& d, ull a, ull b) {
    asm("fma.rn.f32x2 %0, %1, %2, %0;" : "+l"(d) : "l"(a), "l"(b));
}

__device__ __forceinline__ float sigm(float v) {
    return __fdividef(1.f, 1.f + __expf(-v));
}
__device__ __forceinline__ float tanhv(float v) {
    v = fminf(fmaxf(v, -20.f), 20.f);
    float e = __expf(-2.f * v);
    return __fdividef(1.f - e, 1.f + e);
}

// ---------------------------------------------------------------------------
// Pack kernel: build g_B and g_bias.
// ---------------------------------------------------------------------------
__global__ void pack_kernel(
    const float* __restrict__ Wi, const float* __restrict__ Wf,
    const float* __restrict__ Wc, const float* __restrict__ Wo,
    const float* __restrict__ Ci, const float* __restrict__ Cf,
    const float* __restrict__ Cc, const float* __restrict__ Co,
    const float* __restrict__ cbi, const float* __restrict__ cbf,
    const float* __restrict__ cbc, const float* __restrict__ cbo,
    const float* __restrict__ bi, const float* __restrict__ bf,
    const float* __restrict__ bc, const float* __restrict__ bo)
{
    int idx = blockIdx.x * blockDim.x + threadIdx.x;
    if (idx < 144 * 512) {
        int k = idx >> 9, col = idx & 511;
        int g = col >> 7, j = col & 127;
        const float* W = (g == 0) ? Wi : (g == 1) ? Wf : (g == 2) ? Wc : Wo;
        const float* C = (g == 0) ? Ci : (g == 1) ? Cf : (g == 2) ? Cc : Co;
        g_B[idx] = (k < 16) ? W[k * 128 + j] : C[(k - 16) * 128 + j];
    } else if (idx < 144 * 512 + 512) {
        int col = idx - 144 * 512;
        int g = col >> 7, j = col & 127;
        const float* cb = (g == 0) ? cbi : (g == 1) ? cbf : (g == 2) ? cbc : cbo;
        const float* bb = (g == 0) ? bi  : (g == 1) ? bf  : (g == 2) ? bc  : bo;
        g_bias[col] = cb[j] + bb[j];
    }
}

// ---------------------------------------------------------------------------
// Fused gates kernel: per-CTA 64 rows x 512 gate-columns GEMM (K=144) with the
// LSTM elementwise math fused into the epilogue. 512 threads; each thread owns
// 8 rows x (2 cols x 4 gates) accumulators in packed f32x2 registers.
// ---------------------------------------------------------------------------
__global__ __launch_bounds__(512, 1)
void gates_kernel(const float* __restrict__ x, const float* __restrict__ h,
                  const float* __restrict__ c,
                  const float* __restrict__ wci, const float* __restrict__ wcf,
                  const float* __restrict__ wco,
                  float* __restrict__ outh, float* __restrict__ outc, int N)
{
    __shared__ float As[16][64];     // [k][row]
    __shared__ float Bs[16][512];    // [k][col]

    const int tid  = threadIdx.x;
    const int row0 = blockIdx.x * 64;
    const int ty   = tid >> 6;       // 0..7  -> row group
    const int tx   = tid & 63;       // 0..63 -> col pair
    const int r0   = ty * 8;
    const int j0   = tx * 2;

    ull acc[8][4];
    #pragma unroll
    for (int g = 0; g < 4; ++g) {
        ull bv = *(const ull*)&g_bias[g * 128 + j0];
        #pragma unroll
        for (int r = 0; r < 8; ++r) acc[r][g] = bv;
    }

    for (int kc = 0; kc < 9; ++kc) {
        __syncthreads();
        // Load A tile: k-chunk 0 comes from x (16 cols), chunks 1..8 from h.
        if (tid < 256) {
            int r = tid >> 2, q = tid & 3;
            int grow = row0 + r; if (grow >= N) grow = N - 1;
            float4 v;
            if (kc == 0) v = *(const float4*)&x[grow * 16 + q * 4];
            else         v = *(const float4*)&h[grow * 128 + (kc - 1) * 16 + q * 4];
            As[q * 4 + 0][r] = v.x; As[q * 4 + 1][r] = v.y;
            As[q * 4 + 2][r] = v.z; As[q * 4 + 3][r] = v.w;
        }
        // Load B tile (16 x 512) from packed weights (L2-resident).
        {
            int k = tid >> 5;                 // 0..15
            int cb = (tid & 31) * 16;         // 0..496
            const float4* src = (const float4*)&g_B[(kc * 16 + k) * 512 + cb];
            float4* dst = (float4*)&Bs[k][cb];
            #pragma unroll
            for (int i = 0; i < 4; ++i) dst[i] = src[i];
        }
        __syncthreads();

        #pragma unroll
        for (int k = 0; k < 16; ++k) {
            float4 a0 = *(const float4*)&As[k][r0];
            float4 a1 = *(const float4*)&As[k][r0 + 4];
            float ar[8] = {a0.x, a0.y, a0.z, a0.w, a1.x, a1.y, a1.z, a1.w};
            ull b[4];
            #pragma unroll
            for (int g = 0; g < 4; ++g)
                b[g] = *(const ull*)&Bs[k][g * 128 + j0];
            #pragma unroll
            for (int r = 0; r < 8; ++r) {
                ull a2 = pack2(ar[r], ar[r]);
                #pragma unroll
                for (int g = 0; g < 4; ++g) fma2(acc[r][g], a2, b[g]);
            }
        }
    }

    // Epilogue: full GCLSTM cell math, in-register per (row, col-pair).
    float2 pci = *(const float2*)&wci[j0];
    float2 pcf = *(const float2*)&wcf[j0];
    float2 pco = *(const float2*)&wco[j0];
    #pragma unroll
    for (int r = 0; r < 8; ++r) {
        int grow = row0 + r0 + r;
        if (grow >= N) break;
        float2 c2 = *(const float2*)&c[grow * 128 + j0];
        float pix, piy, pfx, pfy, pcx, pcy, pox, poy;
        unpack2(acc[r][0], pix, piy);
        unpack2(acc[r][1], pfx, pfy);
        unpack2(acc[r][2], pcx, pcy);
        unpack2(acc[r][3], pox, poy);
        float ix = sigm(pix + pci.x * c2.x), iy = sigm(piy + pci.y * c2.y);
        float fx = sigm(pfx + pcf.x * c2.x), fy = sigm(pfy + pcf.y * c2.y);
        float tx_ = tanhv(pcx),              ty_ = tanhv(pcy);
        float cnx = fx * c2.x + ix * tx_,    cny = fy * c2.y + iy * ty_;
        float ox = sigm(pox + pco.x * cnx),  oy = sigm(poy + pco.y * cny);
        float hnx = ox * tanhv(cnx),         hny = oy * tanhv(cny);
        *(float2*)&outh[grow * 128 + j0] = make_float2(hnx, hny);
        *(float2*)&outc[grow * 128 + j0] = make_float2(cnx, cny);
    }
}

// ---------------------------------------------------------------------------
// MLP head: relu(h_new) -> 64 -> relu -> 64 -> relu -> 1. Fully fused; 64 rows
// per CTA; weights + activations staged in dynamic shared memory.
// ---------------------------------------------------------------------------
// smem float layout:
//  sW1 [128*64]      @ 0
//  sW2 [64*64]       @ 8192
//  sW3 [64]          @ 12288
//  sB1 [64]          @ 12352
//  sB2 [64]          @ 12416
//  sH  [64*132]      @ 12480   (relu(h)), reused as sL2 [64*68]
//  sL1 [64*68]       @ 20928
// total 25280 floats = 101120 bytes
#define MLP_SMEM_BYTES 101120

__global__ __launch_bounds__(256)
void mlp_kernel(const float* __restrict__ hsrc,
                const float* __restrict__ w1, const float* __restrict__ b1,
                const float* __restrict__ w2, const float* __restrict__ b2,
                const float* __restrict__ w3, const float* __restrict__ b3,
                float* __restrict__ out, int N)
{
    extern __shared__ float sm[];
    float* sW1 = sm;
    float* sW2 = sm + 8192;
    float* sW3 = sm + 12288;
    float* sB1 = sm + 12352;
    float* sB2 = sm + 12416;
    float* sH  = sm + 12480;     // stride 132
    float* sL1 = sm + 20928;     // stride 68
    float* sL2 = sH;             // stride 68 (reuse after layer 1)

    const int tid  = threadIdx.x;
    const int row0 = blockIdx.x * 64;

    #pragma unroll
    for (int i = 0; i < 8; ++i)
        ((float4*)sW1)[tid + i * 256] = ((const float4*)w1)[tid + i * 256];
    #pragma unroll
    for (int i = 0; i < 4; ++i)
        ((float4*)sW2)[tid + i * 256] = ((const float4*)w2)[tid + i * 256];
    if (tid < 64) { sW3[tid] = w3[tid]; sB1[tid] = b1[tid]; sB2[tid] = b2[tid]; }
    {
        int r = tid >> 2, q = tid & 3;
        int grow = row0 + r; if (grow >= N) grow = N - 1;
        #pragma unroll
        for (int i = 0; i < 8; ++i) {
            float4 v = *(const float4*)&hsrc[grow * 128 + q * 32 + i * 4];
            v.x = fmaxf(v.x, 0.f); v.y = fmaxf(v.y, 0.f);
            v.z = fmaxf(v.z, 0.f); v.w = fmaxf(v.w, 0.f);
            *(float4*)&sH[r * 132 + q * 32 + i * 4] = v;
        }
    }
    __syncthreads();

    const int to = (tid & 15) * 4;   // 4 output cols
    const int tr = (tid >> 4) * 4;   // 4 rows

    // Layer 1: 128 -> 64
    {
        ull ib0 = *(const ull*)&sB1[to];
        ull ib1 = *(const ull*)&sB1[to + 2];
        ull acc[4][2];
        #pragma unroll
        for (int i = 0; i < 4; ++i) { acc[i][0] = ib0; acc[i][1] = ib1; }
        #pragma unroll 8
        for (int k = 0; k < 128; ++k) {
            const ull* pw = (const ull*)&sW1[k * 64 + to];
            ull w0 = pw[0], wv = pw[1];
            #pragma unroll
            for (int i = 0; i < 4; ++i) {
                ull a2 = pack2(sH[(tr + i) * 132 + k], sH[(tr + i) * 132 + k]);
                fma2(acc[i][0], a2, w0);
                fma2(acc[i][1], a2, wv);
            }
        }
        #pragma unroll
        for (int i = 0; i < 4; ++i) {
            float v0, v1, v2, v3;
            unpack2(acc[i][0], v0, v1); unpack2(acc[i][1], v2, v3);
            *(float4*)&sL1[(tr + i) * 68 + to] =
                make_float4(fmaxf(v0, 0.f), fmaxf(v1, 0.f),
                            fmaxf(v2, 0.f), fmaxf(v3, 0.f));
        }
    }
    __syncthreads();

    // Layer 2: 64 -> 64 (writes into sL2 == sH region)
    {
        ull ib0 = *(const ull*)&sB2[to];
        ull ib1 = *(const ull*)&sB2[to + 2];
        ull acc[4][2];
        #pragma unroll
        for (int i = 0; i < 4; ++i) { acc[i][0] = ib0; acc[i][1] = ib1; }
        #pragma unroll 8
        for (int k = 0; k < 64; ++k) {
            const ull* pw = (const ull*)&sW2[k * 64 + to];
            ull w0 = pw[0], wv = pw[1];
            #pragma unroll
            for (int i = 0; i < 4; ++i) {
                ull a2 = pack2(sL1[(tr + i) * 68 + k], sL1[(tr + i) * 68 + k]);
                fma2(acc[i][0], a2, w0);
                fma2(acc[i][1], a2, wv);
            }
        }
        __syncthreads();   // ensure sH reads (layer1) done before overwrite
        #pragma unroll
        for (int i = 0; i < 4; ++i) {
            float v0, v1, v2, v3;
            unpack2(acc[i][0], v0, v1); unpack2(acc[i][1], v2, v3);
            *(float4*)&sL2[(tr + i) * 68 + to] =
                make_float4(fmaxf(v0, 0.f), fmaxf(v1, 0.f),
                            fmaxf(v2, 0.f), fmaxf(v3, 0.f));
        }
    }
    __syncthreads();

    // Layer 3: 64 -> 1
    if (tid < 64) {
        int grow = row0 + tid;
        if (grow < N) {
            float a = b3[0];
            #pragma unroll
            for (int k = 0; k < 64; ++k) a += sL2[tid * 68 + k] * sW3[k];
            out[grow] = a;
        }
    }
}

// ---------------------------------------------------------------------------
extern "C" void kernel_launch(void* const* d_in, const int* in_sizes, int n_in,
                              void* d_out, int out_size)
{
    const float* x   = (const float*)d_in[0];
    const float* h   = (const float*)d_in[3];
    const float* c   = (const float*)d_in[4];
    const float* Wi  = (const float*)d_in[5];
    const float* Wf  = (const float*)d_in[6];
    const float* Wc  = (const float*)d_in[7];
    const float* Wo  = (const float*)d_in[8];
    const float* Ci  = (const float*)d_in[9];
    const float* Cf  = (const float*)d_in[10];
    const float* Cc  = (const float*)d_in[11];
    const float* Co  = (const float*)d_in[12];
    const float* cbi = (const float*)d_in[13];
    const float* cbf = (const float*)d_in[14];
    const float* cbc = (const float*)d_in[15];
    const float* cbo = (const float*)d_in[16];
    const float* wci = (const float*)d_in[17];
    const float* wcf = (const float*)d_in[18];
    const float* wco = (const float*)d_in[19];
    const float* bi  = (const float*)d_in[20];
    const float* bf  = (const float*)d_in[21];
    const float* bc  = (const float*)d_in[22];
    const float* bo  = (const float*)d_in[23];
    const float* w1  = (const float*)d_in[24];
    const float* b1  = (const float*)d_in[25];
    const float* w2  = (const float*)d_in[26];
    const float* b2  = (const float*)d_in[27];
    const float* w3  = (const float*)d_in[28];
    const float* b3  = (const float*)d_in[29];

    const int N = in_sizes[3] / 128;

    float* out  = (float*)d_out;
    float* outh = out + N;
    float* outc = outh + (size_t)N * 128;

    pack_kernel<<<(144 * 512 + 512 + 255) / 256, 256>>>(
        Wi, Wf, Wc, Wo, Ci, Cf, Cc, Co,
        cbi, cbf, cbc, cbo, bi, bf, bc, bo);

    gates_kernel<<<(N + 63) / 64, 512>>>(x, h, c, wci, wcf, wco, outh, outc, N);

    cudaFuncSetAttribute(mlp_kernel,
                         cudaFuncAttributeMaxDynamicSharedMemorySize,
                         MLP_SMEM_BYTES);
    mlp_kernel<<<(N + 63) / 64, 256, MLP_SMEM_BYTES>>>(
        outh, w1, b1, w2, b2, w3, b3, out, N);
}

// round 3
// speedup vs baseline: 1.4448x; 1.4448x over previous
#include <cuda_runtime.h>
#include <cstdint>

// ---------------------------------------------------------------------------
// RecurrentGCN (GCLSTM + MLP head).
// Gates GEMM via mma.sync tf32 (sm_80-style PTX; tcgen05 rejected by harness's
// sm_103 PTX target). Gate-interleaved B packing -> fused register epilogue.
// d_out: out[N] | h_new[N,128] | c_new[N,128]
// ---------------------------------------------------------------------------

typedef unsigned long long ull;

// B packed fragment-major: [s(18)][wg(4)][t(16)][lane(32)][half(2)] tf32 bits.
// pcol = j*4 + g (gate-interleaved); per frag: b0 k=8s+lane%4, b1 k+4,
// col n = lane/4 within n8-tile t; wg covers 128 packed cols = 32 j.
__device__ float g_Bp[73728];
__device__ float g_bias[512];          // [g*128+j] = conv_g_b[j] + b_g[j]

// ---------------- helpers --------------------------------------------------
__device__ __forceinline__ float tf32r(float v) {
    uint32_t u;
    asm("cvt.rna.tf32.f32 %0, %1;" : "=r"(u) : "f"(v));
    return __uint_as_float(u);
}
__device__ __forceinline__ void mma8(float& d0, float& d1, float& d2, float& d3,
                                     uint32_t a0, uint32_t a1, uint32_t a2,
                                     uint32_t a3, uint32_t b0, uint32_t b1) {
    asm volatile(
        "mma.sync.aligned.m16n8k8.row.col.f32.tf32.tf32.f32 "
        "{%0,%1,%2,%3},{%4,%5,%6,%7},{%8,%9},{%0,%1,%2,%3};"
        : "+f"(d0), "+f"(d1), "+f"(d2), "+f"(d3)
        : "r"(a0), "r"(a1), "r"(a2), "r"(a3), "r"(b0), "r"(b1));
}
__device__ __forceinline__ ull pack2(float x, float y) {
    ull r; asm("mov.b64 %0, {%1, %2};" : "=l"(r) : "f"(x), "f"(y)); return r;
}
__device__ __forceinline__ void unpack2(ull v, float& x, float& y) {
    asm("mov.b64 {%0, %1}, %2;" : "=f"(x), "=f"(y) : "l"(v));
}
__device__ __forceinline__ void fma2(ull& d, ull a, ull b) {
    asm("fma.rn.f32x2 %0, %1, %2, %0;" : "+l"(d) : "l"(a), "l"(b));
}
__device__ __forceinline__ float sigm(float v) {
    return __fdividef(1.f, 1.f + __expf(-v));
}
__device__ __forceinline__ float tanhv(float v) {
    v = fminf(fmaxf(v, -20.f), 20.f);
    float e = __expf(-2.f * v);
    return __fdividef(1.f - e, 1.f + e);
}

// ---------------------------------------------------------------------------
// Pack kernel: B fragments (tf32-rounded) + fused bias.
// ---------------------------------------------------------------------------
__global__ void pack_kernel(
    const float* __restrict__ Wi, const float* __restrict__ Wf,
    const float* __restrict__ Wc, const float* __restrict__ Wo,
    const float* __restrict__ Ci, const float* __restrict__ Cf,
    const float* __restrict__ Cc, const float* __restrict__ Co,
    const float* __restrict__ cbi, const float* __restrict__ cbf,
    const float* __restrict__ cbc, const float* __restrict__ cbo,
    const float* __restrict__ bi, const float* __restrict__ bf,
    const float* __restrict__ bc, const float* __restrict__ bo)
{
    int idx = blockIdx.x * blockDim.x + threadIdx.x;
    if (idx < 73728) {
        int half = idx & 1;
        int l    = (idx >> 1) & 31;
        int t    = (idx >> 6) & 15;
        int wg   = (idx >> 10) & 3;
        int s    = idx >> 12;
        int k    = s * 8 + (l & 3) + half * 4;          // 0..143
        int pcol = wg * 128 + t * 8 + (l >> 2);
        int j = pcol >> 2, g = pcol & 3;
        const float* W = (g == 0) ? Wi : (g == 1) ? Wf : (g == 2) ? Wc : Wo;
        const float* C = (g == 0) ? Ci : (g == 1) ? Cf : (g == 2) ? Cc : Co;
        float v = (k < 16) ? W[k * 128 + j] : C[(k - 16) * 128 + j];
        g_Bp[idx] = tf32r(v);
    } else if (idx < 73728 + 512) {
        int col = idx - 73728;
        int g = col >> 7, j = col & 127;
        const float* cb = (g == 0) ? cbi : (g == 1) ? cbf : (g == 2) ? cbc : cbo;
        const float* bb = (g == 0) ? bi  : (g == 1) ? bf  : (g == 2) ? bc  : bo;
        g_bias[col] = cb[j] + bb[j];
    }
}

// ---------------------------------------------------------------------------
// Gates kernel: 128 rows x 512 cols per CTA, mma.sync tf32, fused epilogue.
// smem (floats): sA[128*148] @0, sBias[512] @18944, sPeep[384] @19456,
//                sB[3*2048] @19840.  Total 25984 floats = 103936 B.
// ---------------------------------------------------------------------------
#define GATES_SMEM_BYTES 103936

__global__ __launch_bounds__(256, 1)
void gates_mma(const float* __restrict__ x, const float* __restrict__ h,
               const float* __restrict__ c,
               const float* __restrict__ wci, const float* __restrict__ wcf,
               const float* __restrict__ wco,
               float* __restrict__ outh, float* __restrict__ outc, int N)
{
    extern __shared__ float sm[];
    float* sA    = sm;            // [row][k] stride 148
    float* sBias = sm + 18944;
    float* sPeep = sm + 19456;
    float* sB    = sm + 19840;    // 3 x [wg2][t16][lane32][2]

    const int tid   = threadIdx.x;
    const int lane  = tid & 31;
    const int wid   = tid >> 5;
    const int warpM = wid >> 1;         // 0..3
    const int warpN = wid & 1;          // 0..1
    const int g4    = lane >> 2;        // 0..7
    const int tg    = lane & 3;         // 0..3
    const int row0  = blockIdx.x * 128;

    // Stage A (x|h), tf32-rounded.
    for (int i = tid; i < 128 * 36; i += 256) {
        int r = i / 36, q = i - r * 36;
        int grow = row0 + r; if (grow >= N) grow = N - 1;
        float4 v = (q < 4) ? ((const float4*)x)[grow * 4 + q]
                           : ((const float4*)h)[(size_t)grow * 32 + (q - 4)];
        v.x = tf32r(v.x); v.y = tf32r(v.y); v.z = tf32r(v.z); v.w = tf32r(v.w);
        *(float4*)&sA[r * 148 + q * 4] = v;
    }
    sBias[tid] = g_bias[tid]; sBias[256 + tid] = g_bias[256 + tid];
    if (tid < 128) {
        sPeep[tid] = wci[tid]; sPeep[128 + tid] = wcf[tid];
        sPeep[256 + tid] = wco[tid];
    }
    __syncthreads();

    const float* aBase = &sA[(warpM * 32 + g4) * 148 + tg];

    for (int pass = 0; pass < 2; ++pass) {
        float acc[2][16][4];
        #pragma unroll
        for (int m = 0; m < 2; ++m)
            #pragma unroll
            for (int t = 0; t < 16; ++t)
                #pragma unroll
                for (int e = 0; e < 4; ++e) acc[m][t][e] = 0.f;

        const float* gsrc = g_Bp + (size_t)(pass * 2) * 1024;

        // prefetch s = 0 into buffer 0
        {
            const float4* src = (const float4*)gsrc;
            float4 p0 = src[tid * 2], p1 = src[tid * 2 + 1];
            *(float4*)&sB[tid * 8] = p0;
            *(float4*)&sB[tid * 8 + 4] = p1;
        }
        __syncthreads();

        #pragma unroll 3
        for (int s = 0; s < 18; ++s) {
            float4 n0, n1;
            if (s < 17) {
                const float4* src = (const float4*)(gsrc + (size_t)(s + 1) * 4096);
                n0 = src[tid * 2]; n1 = src[tid * 2 + 1];
            }
            uint32_t a[2][4];
            const float* ab = aBase + s * 8;
            #pragma unroll
            for (int m = 0; m < 2; ++m) {
                a[m][0] = __float_as_uint(ab[m * 16 * 148]);
                a[m][1] = __float_as_uint(ab[m * 16 * 148 + 8 * 148]);
                a[m][2] = __float_as_uint(ab[m * 16 * 148 + 4]);
                a[m][3] = __float_as_uint(ab[m * 16 * 148 + 8 * 148 + 4]);
            }
            const float* bb = &sB[(s % 3) * 2048 + warpN * 1024 + lane * 2];
            #pragma unroll
            for (int t = 0; t < 16; ++t) {
                float2 b = *(const float2*)&bb[t * 64];
                uint32_t b0 = __float_as_uint(b.x), b1 = __float_as_uint(b.y);
                mma8(acc[0][t][0], acc[0][t][1], acc[0][t][2], acc[0][t][3],
                     a[0][0], a[0][1], a[0][2], a[0][3], b0, b1);
                mma8(acc[1][t][0], acc[1][t][1], acc[1][t][2], acc[1][t][3],
                     a[1][0], a[1][1], a[1][2], a[1][3], b0, b1);
            }
            if (s < 17) {
                float* d = &sB[((s + 1) % 3) * 2048 + tid * 8];
                *(float4*)d = n0; *(float4*)&d[4] = n1;
            }
            __syncthreads();
        }

        // Epilogue: pair-exchange gates, full GCLSTM cell math.
        const int wgp = pass * 2 + warpN;
        #pragma unroll
        for (int m = 0; m < 2; ++m) {
            const int rbase = warpM * 32 + m * 16 + g4;
            #pragma unroll
            for (int t = 0; t < 16; ++t) {
                float c0 = acc[m][t][0], c1 = acc[m][t][1];
                float c2 = acc[m][t][2], c3 = acc[m][t][3];
                float o0 = __shfl_xor_sync(0xffffffffu, c0, 1);
                float o1 = __shfl_xor_sync(0xffffffffu, c1, 1);
                float o2 = __shfl_xor_sync(0xffffffffu, c2, 1);
                float o3 = __shfl_xor_sync(0xffffffffu, c3, 1);
                int j = wgp * 32 + t * 2 + (tg >> 1);
                int odd = lane & 1;
                int r = odd ? rbase + 8 : rbase;
                float gi = odd ? o2 : c0;
                float gf = odd ? o3 : c1;
                float gc = odd ? c2 : o0;
                float go = odd ? c3 : o1;
                int grow = row0 + r;
                if (grow < N) {
                    float co = c[(size_t)grow * 128 + j];
                    float pi = gi + sBias[j]       + sPeep[j] * co;
                    float pf = gf + sBias[128 + j] + sPeep[128 + j] * co;
                    float pc = gc + sBias[256 + j];
                    float po = go + sBias[384 + j];
                    float iv = sigm(pi), fv = sigm(pf), tv = tanhv(pc);
                    float cn = fv * co + iv * tv;
                    float ov = sigm(po + sPeep[256 + j] * cn);
                    outh[(size_t)grow * 128 + j] = ov * tanhv(cn);
                    outc[(size_t)grow * 128 + j] = cn;
                }
            }
        }
        __syncthreads();
    }
}

// ---------------------------------------------------------------------------
// MLP head (round-1 validated): relu -> 64 -> relu -> 64 -> relu -> 1.
// ---------------------------------------------------------------------------
#define MLP_SMEM_BYTES 101120

__global__ __launch_bounds__(256)
void mlp_kernel(const float* __restrict__ hsrc,
                const float* __restrict__ w1, const float* __restrict__ b1,
                const float* __restrict__ w2, const float* __restrict__ b2,
                const float* __restrict__ w3, const float* __restrict__ b3,
                float* __restrict__ out, int N)
{
    extern __shared__ float smf[];
    float* sW1 = smf;
    float* sW2 = smf + 8192;
    float* sW3 = smf + 12288;
    float* sB1 = smf + 12352;
    float* sB2 = smf + 12416;
    float* sH  = smf + 12480;     // stride 132
    float* sL1 = smf + 20928;     // stride 68
    float* sL2 = sH;              // stride 68 (reuse)

    const int tid  = threadIdx.x;
    const int row0 = blockIdx.x * 64;

    #pragma unroll
    for (int i = 0; i < 8; ++i)
        ((float4*)sW1)[tid + i * 256] = ((const float4*)w1)[tid + i * 256];
    #pragma unroll
    for (int i = 0; i < 4; ++i)
        ((float4*)sW2)[tid + i * 256] = ((const float4*)w2)[tid + i * 256];
    if (tid < 64) { sW3[tid] = w3[tid]; sB1[tid] = b1[tid]; sB2[tid] = b2[tid]; }
    {
        int r = tid >> 2, q = tid & 3;
        int grow = row0 + r; if (grow >= N) grow = N - 1;
        #pragma unroll
        for (int i = 0; i < 8; ++i) {
            float4 v = *(const float4*)&hsrc[(size_t)grow * 128 + q * 32 + i * 4];
            v.x = fmaxf(v.x, 0.f); v.y = fmaxf(v.y, 0.f);
            v.z = fmaxf(v.z, 0.f); v.w = fmaxf(v.w, 0.f);
            *(float4*)&sH[r * 132 + q * 32 + i * 4] = v;
        }
    }
    __syncthreads();

    const int to = (tid & 15) * 4;
    const int tr = (tid >> 4) * 4;

    {
        ull ib0 = *(const ull*)&sB1[to];
        ull ib1 = *(const ull*)&sB1[to + 2];
        ull acc[4][2];
        #pragma unroll
        for (int i = 0; i < 4; ++i) { acc[i][0] = ib0; acc[i][1] = ib1; }
        #pragma unroll 8
        for (int k = 0; k < 128; ++k) {
            const ull* pw = (const ull*)&sW1[k * 64 + to];
            ull w0 = pw[0], wv = pw[1];
            #pragma unroll
            for (int i = 0; i < 4; ++i) {
                ull a2 = pack2(sH[(tr + i) * 132 + k], sH[(tr + i) * 132 + k]);
                fma2(acc[i][0], a2, w0);
                fma2(acc[i][1], a2, wv);
            }
        }
        #pragma unroll
        for (int i = 0; i < 4; ++i) {
            float v0, v1, v2, v3;
            unpack2(acc[i][0], v0, v1); unpack2(acc[i][1], v2, v3);
            *(float4*)&sL1[(tr + i) * 68 + to] =
                make_float4(fmaxf(v0, 0.f), fmaxf(v1, 0.f),
                            fmaxf(v2, 0.f), fmaxf(v3, 0.f));
        }
    }
    __syncthreads();

    {
        ull ib0 = *(const ull*)&sB2[to];
        ull ib1 = *(const ull*)&sB2[to + 2];
        ull acc[4][2];
        #pragma unroll
        for (int i = 0; i < 4; ++i) { acc[i][0] = ib0; acc[i][1] = ib1; }
        #pragma unroll 8
        for (int k = 0; k < 64; ++k) {
            const ull* pw = (const ull*)&sW2[k * 64 + to];
            ull w0 = pw[0], wv = pw[1];
            #pragma unroll
            for (int i = 0; i < 4; ++i) {
                ull a2 = pack2(sL1[(tr + i) * 68 + k], sL1[(tr + i) * 68 + k]);
                fma2(acc[i][0], a2, w0);
                fma2(acc[i][1], a2, wv);
            }
        }
        __syncthreads();
        #pragma unroll
        for (int i = 0; i < 4; ++i) {
            float v0, v1, v2, v3;
            unpack2(acc[i][0], v0, v1); unpack2(acc[i][1], v2, v3);
            *(float4*)&sL2[(tr + i) * 68 + to] =
                make_float4(fmaxf(v0, 0.f), fmaxf(v1, 0.f),
                            fmaxf(v2, 0.f), fmaxf(v3, 0.f));
        }
    }
    __syncthreads();

    if (tid < 64) {
        int grow = row0 + tid;
        if (grow < N) {
            float a = b3[0];
            #pragma unroll
            for (int k = 0; k < 64; ++k) a += sL2[tid * 68 + k] * sW3[k];
            out[grow] = a;
        }
    }
}

// ---------------------------------------------------------------------------
extern "C" void kernel_launch(void* const* d_in, const int* in_sizes, int n_in,
                              void* d_out, int out_size)
{
    const float* x   = (const float*)d_in[0];
    const float* h   = (const float*)d_in[3];
    const float* c   = (const float*)d_in[4];
    const float* Wi  = (const float*)d_in[5];
    const float* Wf  = (const float*)d_in[6];
    const float* Wc  = (const float*)d_in[7];
    const float* Wo  = (const float*)d_in[8];
    const float* Ci  = (const float*)d_in[9];
    const float* Cf  = (const float*)d_in[10];
    const float* Cc  = (const float*)d_in[11];
    const float* Co  = (const float*)d_in[12];
    const float* cbi = (const float*)d_in[13];
    const float* cbf = (const float*)d_in[14];
    const float* cbc = (const float*)d_in[15];
    const float* cbo = (const float*)d_in[16];
    const float* wci = (const float*)d_in[17];
    const float* wcf = (const float*)d_in[18];
    const float* wco = (const float*)d_in[19];
    const float* bi  = (const float*)d_in[20];
    const float* bf  = (const float*)d_in[21];
    const float* bc  = (const float*)d_in[22];
    const float* bo  = (const float*)d_in[23];
    const float* w1  = (const float*)d_in[24];
    const float* b1  = (const float*)d_in[25];
    const float* w2  = (const float*)d_in[26];
    const float* b2  = (const float*)d_in[27];
    const float* w3  = (const float*)d_in[28];
    const float* b3  = (const float*)d_in[29];

    const int N = in_sizes[3] / 128;

    float* out  = (float*)d_out;
    float* outh = out + N;
    float* outc = outh + (size_t)N * 128;

    pack_kernel<<<(73728 + 512 + 255) / 256, 256>>>(
        Wi, Wf, Wc, Wo, Ci, Cf, Cc, Co,
        cbi, cbf, cbc, cbo, bi, bf, bc, bo);

    cudaFuncSetAttribute(gates_mma,
                         cudaFuncAttributeMaxDynamicSharedMemorySize,
                         GATES_SMEM_BYTES);
    gates_mma<<<(N + 127) / 128, 256, GATES_SMEM_BYTES>>>(
        x, h, c, wci, wcf, wco, outh, outc, N);

    cudaFuncSetAttribute(mlp_kernel,
                         cudaFuncAttributeMaxDynamicSharedMemorySize,
                         MLP_SMEM_BYTES);
    mlp_kernel<<<(N + 63) / 64, 256, MLP_SMEM_BYTES>>>(
        outh, w1, b1, w2, b2, w3, b3, out, N);
}

// round 4
// speedup vs baseline: 2.0533x; 1.4212x over previous
#include <cuda_runtime.h>
#include <cuda_fp16.h>
#include <cstdint>

// ---------------------------------------------------------------------------
// RecurrentGCN (GCLSTM + MLP head).
// Gates GEMM: fp16 mma.sync m16n8k16 (f32 accum), barrier-free mainloop,
// whole B resident in smem, ldmatrix A-fragments, fused LSTM epilogue.
// d_out: out[N] | h_new[N,128] | c_new[N,128]
// ---------------------------------------------------------------------------

typedef unsigned long long ull;

// B packed fragment-major fp16:
// half index = ((((s*4 + wg)*16 + t)*64) + lane*2 + r)*2 + hh
//   k = s*16 + (lane&3)*2 + r*8 + hh   (K = 144 = 9*16 exactly)
//   pcol = wg*128 + t*8 + (lane>>2);  g = pcol&3, j = pcol>>2
__device__ __half g_Bph[73728];
__device__ float  g_bias[512];          // [g*128+j] = conv_g_b[j] + b_g[j]

// ---------------- helpers --------------------------------------------------
__device__ __forceinline__ uint32_t s2u(const void* p) {
    uint32_t a;
    asm("{ .reg .u64 t; cvta.to.shared.u64 t, %1; cvt.u32.u64 %0, t; }"
        : "=r"(a) : "l"(p));
    return a;
}
__device__ __forceinline__ void mma16(float& d0, float& d1, float& d2, float& d3,
                                      uint32_t a0, uint32_t a1, uint32_t a2,
                                      uint32_t a3, uint32_t b0, uint32_t b1) {
    asm volatile(
        "mma.sync.aligned.m16n8k16.row.col.f32.f16.f16.f32 "
        "{%0,%1,%2,%3},{%4,%5,%6,%7},{%8,%9},{%0,%1,%2,%3};"
        : "+f"(d0), "+f"(d1), "+f"(d2), "+f"(d3)
        : "r"(a0), "r"(a1), "r"(a2), "r"(a3), "r"(b0), "r"(b1));
}
__device__ __forceinline__ void ldm4(uint32_t& r0, uint32_t& r1, uint32_t& r2,
                                     uint32_t& r3, uint32_t addr) {
    asm volatile("ldmatrix.sync.aligned.m8n8.x4.shared.b16 {%0,%1,%2,%3}, [%4];"
                 : "=r"(r0), "=r"(r1), "=r"(r2), "=r"(r3) : "r"(addr));
}
__device__ __forceinline__ ull pack2(float x, float y) {
    ull r; asm("mov.b64 %0, {%1, %2};" : "=l"(r) : "f"(x), "f"(y)); return r;
}
__device__ __forceinline__ void unpack2(ull v, float& x, float& y) {
    asm("mov.b64 {%0, %1}, %2;" : "=f"(x), "=f"(y) : "l"(v));
}
__device__ __forceinline__ void fma2(ull& d, ull a, ull b) {
    asm("fma.rn.f32x2 %0, %1, %2, %0;" : "+l"(d) : "l"(a), "l"(b));
}
__device__ __forceinline__ float sigm(float v) {
    return __fdividef(1.f, 1.f + __expf(-v));
}
__device__ __forceinline__ float tanhv(float v) {
    v = fminf(fmaxf(v, -20.f), 20.f);
    float e = __expf(-2.f * v);
    return __fdividef(1.f - e, 1.f + e);
}
__device__ __forceinline__ uint32_t f2h2(float a, float b) {
    __half2 h = __floats2half2_rn(a, b);
    return *(uint32_t*)&h;
}

// ---------------------------------------------------------------------------
// Pack kernel: B fragments (fp16) + fused bias.
// ---------------------------------------------------------------------------
__global__ void pack_kernel(
    const float* __restrict__ Wi, const float* __restrict__ Wf,
    const float* __restrict__ Wc, const float* __restrict__ Wo,
    const float* __restrict__ Ci, const float* __restrict__ Cf,
    const float* __restrict__ Cc, const float* __restrict__ Co,
    const float* __restrict__ cbi, const float* __restrict__ cbf,
    const float* __restrict__ cbc, const float* __restrict__ cbo,
    const float* __restrict__ bi, const float* __restrict__ bf,
    const float* __restrict__ bc, const float* __restrict__ bo)
{
    int idx = blockIdx.x * blockDim.x + threadIdx.x;
    if (idx < 73728) {
        int hh   = idx & 1;
        int r    = (idx >> 1) & 1;
        int lane = (idx >> 2) & 31;
        int t    = (idx >> 7) & 15;
        int wg   = (idx >> 11) & 3;
        int s    = idx >> 13;
        int k    = s * 16 + (lane & 3) * 2 + r * 8 + hh;    // 0..143
        int pcol = wg * 128 + t * 8 + (lane >> 2);
        int j = pcol >> 2, g = pcol & 3;
        const float* W = (g == 0) ? Wi : (g == 1) ? Wf : (g == 2) ? Wc : Wo;
        const float* C = (g == 0) ? Ci : (g == 1) ? Cf : (g == 2) ? Cc : Co;
        float v = (k < 16) ? W[k * 128 + j] : C[(k - 16) * 128 + j];
        g_Bph[idx] = __float2half_rn(v);
    } else if (idx < 73728 + 512) {
        int col = idx - 73728;
        int g = col >> 7, j = col & 127;
        const float* cb = (g == 0) ? cbi : (g == 1) ? cbf : (g == 2) ? cbc : cbo;
        const float* bb = (g == 0) ? bi  : (g == 1) ? bf  : (g == 2) ? bc  : bo;
        g_bias[col] = cb[j] + bb[j];
    }
}

// ---------------------------------------------------------------------------
// Gates kernel: 128 rows x 512 cols per CTA, fp16 m16n8k16, no mainloop
// barriers. smem (bytes):
//   sAh  [128 rows x 152 halves]  @ 0        (38912 B; ldmatrix conflict-free)
//   sB   [36864 u32 fragments]    @ 38912    (147456 B)
//   sBias[512 f]                  @ 186368
//   sPeep[384 f]                  @ 188416
// total 189952 B
// ---------------------------------------------------------------------------
#define GA_SA    0
#define GA_SB    38912
#define GA_BIAS  186368
#define GA_PEEP  188416
#define GATES_SMEM_BYTES 189952

__global__ __launch_bounds__(256, 1)
void gates_mma(const float* __restrict__ x, const float* __restrict__ h,
               const float* __restrict__ c,
               const float* __restrict__ wci, const float* __restrict__ wcf,
               const float* __restrict__ wco,
               float* __restrict__ outh, float* __restrict__ outc, int N)
{
    extern __shared__ char sm[];
    char*  sA    = sm + GA_SA;
    const uint32_t* sBu = (const uint32_t*)(sm + GA_SB);
    float* sBias = (float*)(sm + GA_BIAS);
    float* sPeep = (float*)(sm + GA_PEEP);

    const int tid   = threadIdx.x;
    const int lane  = tid & 31;
    const int wid   = tid >> 5;
    const int warpM = wid >> 1;         // 0..3
    const int warpN = wid & 1;          // 0..1
    const int g4    = lane >> 2;        // 0..7
    const int tg    = lane & 3;         // 0..3
    const int row0  = blockIdx.x * 128;

    // ---- Stage A as fp16: 128 rows x 144 halves, stride 152 halves (304B) --
    #pragma unroll
    for (int ii = 0; ii < 9; ++ii) {
        int i = tid + ii * 256;                  // 0..2303
        int row = i / 18, ch = i % 18;
        int grow = row0 + row; if (grow >= N) grow = N - 1;
        float4 v0, v1;
        if (ch < 2) {
            const float4* p = (const float4*)&x[(size_t)grow * 16 + ch * 8];
            v0 = p[0]; v1 = p[1];
        } else {
            const float4* p = (const float4*)&h[(size_t)grow * 128 + ch * 8 - 16];
            v0 = p[0]; v1 = p[1];
        }
        uint4 o;
        o.x = f2h2(v0.x, v0.y); o.y = f2h2(v0.z, v0.w);
        o.z = f2h2(v1.x, v1.y); o.w = f2h2(v1.z, v1.w);
        *(uint4*)(sA + row * 304 + ch * 16) = o;
    }
    // ---- Stage B: straight 144KB copy (L2-resident after first waves) ------
    {
        const uint4* src = (const uint4*)g_Bph;
        uint4* dst = (uint4*)(sm + GA_SB);
        #pragma unroll
        for (int ii = 0; ii < 36; ++ii) dst[tid + ii * 256] = src[tid + ii * 256];
    }
    sBias[tid] = g_bias[tid]; sBias[256 + tid] = g_bias[256 + tid];
    if (tid < 128) {
        sPeep[tid] = wci[tid]; sPeep[128 + tid] = wcf[tid];
        sPeep[256 + tid] = wco[tid];
    }
    __syncthreads();

    // Per-thread ldmatrix base address (bytes, shared space).
    // lanes 0-15: row rowm+lane, k-off 0; lanes 16-31: row rowm+(lane-16), k-off 8.
    const int lrow = (lane & 15);
    const int lkof = (lane >> 4) * 8;
    const uint32_t aBase = s2u(sA) + (uint32_t)(warpM * 32 + lrow) * 304 + lkof * 2;

    for (int pass = 0; pass < 2; ++pass) {
        const int wgp = pass * 2 + warpN;
        float acc[2][16][4];
        #pragma unroll
        for (int m = 0; m < 2; ++m)
            #pragma unroll
            for (int t = 0; t < 16; ++t)
                #pragma unroll
                for (int e = 0; e < 4; ++e) acc[m][t][e] = 0.f;

        #pragma unroll
        for (int s = 0; s < 9; ++s) {
            uint32_t a[2][4];
            ldm4(a[0][0], a[0][1], a[0][2], a[0][3], aBase + s * 32);
            ldm4(a[1][0], a[1][1], a[1][2], a[1][3], aBase + s * 32 + 16 * 304);
            const uint32_t* bb = sBu + ((s * 4 + wgp) * 16) * 64 + lane * 2;
            #pragma unroll
            for (int t = 0; t < 16; ++t) {
                uint32_t b0 = bb[t * 64], b1 = bb[t * 64 + 1];
                mma16(acc[0][t][0], acc[0][t][1], acc[0][t][2], acc[0][t][3],
                      a[0][0], a[0][1], a[0][2], a[0][3], b0, b1);
                mma16(acc[1][t][0], acc[1][t][1], acc[1][t][2], acc[1][t][3],
                      a[1][0], a[1][1], a[1][2], a[1][3], b0, b1);
            }
        }

        // Epilogue: pair-exchange gates, full GCLSTM cell math (round-3 form).
        #pragma unroll
        for (int m = 0; m < 2; ++m) {
            const int rbase = warpM * 32 + m * 16 + g4;
            #pragma unroll
            for (int t = 0; t < 16; ++t) {
                float c0 = acc[m][t][0], c1 = acc[m][t][1];
                float c2 = acc[m][t][2], c3 = acc[m][t][3];
                float o0 = __shfl_xor_sync(0xffffffffu, c0, 1);
                float o1 = __shfl_xor_sync(0xffffffffu, c1, 1);
                float o2 = __shfl_xor_sync(0xffffffffu, c2, 1);
                float o3 = __shfl_xor_sync(0xffffffffu, c3, 1);
                int j = wgp * 32 + t * 2 + (tg >> 1);
                int odd = lane & 1;
                int r = odd ? rbase + 8 : rbase;
                float gi = odd ? o2 : c0;
                float gf = odd ? o3 : c1;
                float gc = odd ? c2 : o0;
                float go = odd ? c3 : o1;
                int grow = row0 + r;
                if (grow < N) {
                    float co = c[(size_t)grow * 128 + j];
                    float pi = gi + sBias[j]       + sPeep[j] * co;
                    float pf = gf + sBias[128 + j] + sPeep[128 + j] * co;
                    float pc = gc + sBias[256 + j];
                    float po = go + sBias[384 + j];
                    float iv = sigm(pi), fv = sigm(pf), tv = tanhv(pc);
                    float cn = fv * co + iv * tv;
                    float ov = sigm(po + sPeep[256 + j] * cn);
                    outh[(size_t)grow * 128 + j] = ov * tanhv(cn);
                    outc[(size_t)grow * 128 + j] = cn;
                }
            }
        }
    }
}

// ---------------------------------------------------------------------------
// MLP head: relu -> 64 -> relu -> 64 -> relu -> 1, k-vectorized inner loops.
// ---------------------------------------------------------------------------
#define MLP_SMEM_BYTES 101120

__global__ __launch_bounds__(256)
void mlp_kernel(const float* __restrict__ hsrc,
                const float* __restrict__ w1, const float* __restrict__ b1,
                const float* __restrict__ w2, const float* __restrict__ b2,
                const float* __restrict__ w3, const float* __restrict__ b3,
                float* __restrict__ out, int N)
{
    extern __shared__ float smf[];
    float* sW1 = smf;
    float* sW2 = smf + 8192;
    float* sW3 = smf + 12288;
    float* sB1 = smf + 12352;
    float* sB2 = smf + 12416;
    float* sH  = smf + 12480;     // stride 132
    float* sL1 = smf + 20928;     // stride 68
    float* sL2 = sH;              // stride 68 (reuse)

    const int tid  = threadIdx.x;
    const int row0 = blockIdx.x * 64;

    #pragma unroll
    for (int i = 0; i < 8; ++i)
        ((float4*)sW1)[tid + i * 256] = ((const float4*)w1)[tid + i * 256];
    #pragma unroll
    for (int i = 0; i < 4; ++i)
        ((float4*)sW2)[tid + i * 256] = ((const float4*)w2)[tid + i * 256];
    if (tid < 64) { sW3[tid] = w3[tid]; sB1[tid] = b1[tid]; sB2[tid] = b2[tid]; }
    {
        int r = tid >> 2, q = tid & 3;
        int grow = row0 + r; if (grow >= N) grow = N - 1;
        #pragma unroll
        for (int i = 0; i < 8; ++i) {
            float4 v = *(const float4*)&hsrc[(size_t)grow * 128 + q * 32 + i * 4];
            v.x = fmaxf(v.x, 0.f); v.y = fmaxf(v.y, 0.f);
            v.z = fmaxf(v.z, 0.f); v.w = fmaxf(v.w, 0.f);
            *(float4*)&sH[r * 132 + q * 32 + i * 4] = v;
        }
    }
    __syncthreads();

    const int to = (tid & 15) * 4;
    const int tr = (tid >> 4) * 4;

    // Layer 1: 128 -> 64
    {
        ull ib0 = *(const ull*)&sB1[to];
        ull ib1 = *(const ull*)&sB1[to + 2];
        ull acc[4][2];
        #pragma unroll
        for (int i = 0; i < 4; ++i) { acc[i][0] = ib0; acc[i][1] = ib1; }
        #pragma unroll 4
        for (int k4 = 0; k4 < 32; ++k4) {
            ull w0[4], w1v[4];
            #pragma unroll
            for (int kk = 0; kk < 4; ++kk) {
                float4 wv = *(const float4*)&sW1[(k4 * 4 + kk) * 64 + to];
                w0[kk] = pack2(wv.x, wv.y); w1v[kk] = pack2(wv.z, wv.w);
            }
            #pragma unroll
            for (int i = 0; i < 4; ++i) {
                float4 hv = *(const float4*)&sH[(tr + i) * 132 + k4 * 4];
                float hs[4] = {hv.x, hv.y, hv.z, hv.w};
                #pragma unroll
                for (int kk = 0; kk < 4; ++kk) {
                    ull a2 = pack2(hs[kk], hs[kk]);
                    fma2(acc[i][0], a2, w0[kk]);
                    fma2(acc[i][1], a2, w1v[kk]);
                }
            }
        }
        #pragma unroll
        for (int i = 0; i < 4; ++i) {
            float v0, v1, v2, v3;
            unpack2(acc[i][0], v0, v1); unpack2(acc[i][1], v2, v3);
            *(float4*)&sL1[(tr + i) * 68 + to] =
                make_float4(fmaxf(v0, 0.f), fmaxf(v1, 0.f),
                            fmaxf(v2, 0.f), fmaxf(v3, 0.f));
        }
    }
    __syncthreads();

    // Layer 2: 64 -> 64
    {
        ull ib0 = *(const ull*)&sB2[to];
        ull ib1 = *(const ull*)&sB2[to + 2];
        ull acc[4][2];
        #pragma unroll
        for (int i = 0; i < 4; ++i) { acc[i][0] = ib0; acc[i][1] = ib1; }
        #pragma unroll 4
        for (int k4 = 0; k4 < 16; ++k4) {
            ull w0[4], w1v[4];
            #pragma unroll
            for (int kk = 0; kk < 4; ++kk) {
                float4 wv = *(const float4*)&sW2[(k4 * 4 + kk) * 64 + to];
                w0[kk] = pack2(wv.x, wv.y); w1v[kk] = pack2(wv.z, wv.w);
            }
            #pragma unroll
            for (int i = 0; i < 4; ++i) {
                float4 hv = *(const float4*)&sL1[(tr + i) * 68 + k4 * 4];
                float hs[4] = {hv.x, hv.y, hv.z, hv.w};
                #pragma unroll
                for (int kk = 0; kk < 4; ++kk) {
                    ull a2 = pack2(hs[kk], hs[kk]);
                    fma2(acc[i][0], a2, w0[kk]);
                    fma2(acc[i][1], a2, w1v[kk]);
                }
            }
        }
        __syncthreads();   // sL1 reads done before overwriting sL2 (== sH)
        #pragma unroll
        for (int i = 0; i < 4; ++i) {
            float v0, v1, v2, v3;
            unpack2(acc[i][0], v0, v1); unpack2(acc[i][1], v2, v3);
            *(float4*)&sL2[(tr + i) * 68 + to] =
                make_float4(fmaxf(v0, 0.f), fmaxf(v1, 0.f),
                            fmaxf(v2, 0.f), fmaxf(v3, 0.f));
        }
    }
    __syncthreads();

    // Layer 3: 64 -> 1
    if (tid < 64) {
        int grow = row0 + tid;
        if (grow < N) {
            float a = b3[0];
            #pragma unroll
            for (int k = 0; k < 64; ++k) a += sL2[tid * 68 + k] * sW3[k];
            out[grow] = a;
        }
    }
}

// ---------------------------------------------------------------------------
extern "C" void kernel_launch(void* const* d_in, const int* in_sizes, int n_in,
                              void* d_out, int out_size)
{
    const float* x   = (const float*)d_in[0];
    const float* h   = (const float*)d_in[3];
    const float* c   = (const float*)d_in[4];
    const float* Wi  = (const float*)d_in[5];
    const float* Wf  = (const float*)d_in[6];
    const float* Wc  = (const float*)d_in[7];
    const float* Wo  = (const float*)d_in[8];
    const float* Ci  = (const float*)d_in[9];
    const float* Cf  = (const float*)d_in[10];
    const float* Cc  = (const float*)d_in[11];
    const float* Co  = (const float*)d_in[12];
    const float* cbi = (const float*)d_in[13];
    const float* cbf = (const float*)d_in[14];
    const float* cbc = (const float*)d_in[15];
    const float* cbo = (const float*)d_in[16];
    const float* wci = (const float*)d_in[17];
    const float* wcf = (const float*)d_in[18];
    const float* wco = (const float*)d_in[19];
    const float* bi  = (const float*)d_in[20];
    const float* bf  = (const float*)d_in[21];
    const float* bc  = (const float*)d_in[22];
    const float* bo  = (const float*)d_in[23];
    const float* w1  = (const float*)d_in[24];
    const float* b1  = (const float*)d_in[25];
    const float* w2  = (const float*)d_in[26];
    const float* b2  = (const float*)d_in[27];
    const float* w3  = (const float*)d_in[28];
    const float* b3  = (const float*)d_in[29];

    const int N = in_sizes[3] / 128;

    float* out  = (float*)d_out;
    float* outh = out + N;
    float* outc = outh + (size_t)N * 128;

    pack_kernel<<<(73728 + 512 + 255) / 256, 256>>>(
        Wi, Wf, Wc, Wo, Ci, Cf, Cc, Co,
        cbi, cbf, cbc, cbo, bi, bf, bc, bo);

    cudaFuncSetAttribute(gates_mma,
                         cudaFuncAttributeMaxDynamicSharedMemorySize,
                         GATES_SMEM_BYTES);
    gates_mma<<<(N + 127) / 128, 256, GATES_SMEM_BYTES>>>(
        x, h, c, wci, wcf, wco, outh, outc, N);

    cudaFuncSetAttribute(mlp_kernel,
                         cudaFuncAttributeMaxDynamicSharedMemorySize,
                         MLP_SMEM_BYTES);
    mlp_kernel<<<(N + 63) / 64, 256, MLP_SMEM_BYTES>>>(
        outh, w1, b1, w2, b2, w3, b3, out, N);
}

// round 5
// speedup vs baseline: 2.4698x; 1.2029x over previous
#include <cuda_runtime.h>
#include <cuda_fp16.h>
#include <cstdint>

// ---------------------------------------------------------------------------
// RecurrentGCN (GCLSTM + MLP head).
// Gates: fp16 mma.sync m16n8k16 (f32 acc), 64x256 CTA tiles, 2 CTAs/SM,
// barrier-free mainloop, smem-staged coalesced epilogue, fused LSTM math.
// d_out: out[N] | h_new[N,128] | c_new[N,128]
// ---------------------------------------------------------------------------

typedef unsigned long long ull;

// B packed fragment-major fp16:
// half index = ((((s*4 + wg)*16 + t)*64) + lane*2 + r)*2 + hh
//   k = s*16 + (lane&3)*2 + r*8 + hh   (K = 144 = 9*16)
//   pcol = wg*128 + t*8 + (lane>>2);  g = pcol&3, j = pcol>>2
__device__ __half g_Bph[73728];
__device__ float  g_bias[512];          // [g*128+j] = conv_g_b[j] + b_g[j]

// ---------------- helpers --------------------------------------------------
__device__ __forceinline__ uint32_t s2u(const void* p) {
    uint32_t a;
    asm("{ .reg .u64 t; cvta.to.shared.u64 t, %1; cvt.u32.u64 %0, t; }"
        : "=r"(a) : "l"(p));
    return a;
}
__device__ __forceinline__ void mma16(float& d0, float& d1, float& d2, float& d3,
                                      uint32_t a0, uint32_t a1, uint32_t a2,
                                      uint32_t a3, uint32_t b0, uint32_t b1) {
    asm volatile(
        "mma.sync.aligned.m16n8k16.row.col.f32.f16.f16.f32 "
        "{%0,%1,%2,%3},{%4,%5,%6,%7},{%8,%9},{%0,%1,%2,%3};"
        : "+f"(d0), "+f"(d1), "+f"(d2), "+f"(d3)
        : "r"(a0), "r"(a1), "r"(a2), "r"(a3), "r"(b0), "r"(b1));
}
__device__ __forceinline__ void ldm4(uint32_t& r0, uint32_t& r1, uint32_t& r2,
                                     uint32_t& r3, uint32_t addr) {
    asm volatile("ldmatrix.sync.aligned.m8n8.x4.shared.b16 {%0,%1,%2,%3}, [%4];"
                 : "=r"(r0), "=r"(r1), "=r"(r2), "=r"(r3) : "r"(addr));
}
__device__ __forceinline__ ull pack2(float x, float y) {
    ull r; asm("mov.b64 %0, {%1, %2};" : "=l"(r) : "f"(x), "f"(y)); return r;
}
__device__ __forceinline__ void unpack2(ull v, float& x, float& y) {
    asm("mov.b64 {%0, %1}, %2;" : "=f"(x), "=f"(y) : "l"(v));
}
__device__ __forceinline__ void fma2(ull& d, ull a, ull b) {
    asm("fma.rn.f32x2 %0, %1, %2, %0;" : "+l"(d) : "l"(a), "l"(b));
}
__device__ __forceinline__ float sigm(float v) {
    return __fdividef(1.f, 1.f + __expf(-v));
}
__device__ __forceinline__ float tanhv(float v) {
    v = fminf(fmaxf(v, -20.f), 20.f);
    float e = __expf(-2.f * v);
    return __fdividef(1.f - e, 1.f + e);
}
__device__ __forceinline__ uint32_t f2h2(float a, float b) {
    __half2 h = __floats2half2_rn(a, b);
    return *(uint32_t*)&h;
}

// ---------------------------------------------------------------------------
// Pack kernel: B fragments (fp16) + fused bias.  (validated round 4)
// ---------------------------------------------------------------------------
__global__ void pack_kernel(
    const float* __restrict__ Wi, const float* __restrict__ Wf,
    const float* __restrict__ Wc, const float* __restrict__ Wo,
    const float* __restrict__ Ci, const float* __restrict__ Cf,
    const float* __restrict__ Cc, const float* __restrict__ Co,
    const float* __restrict__ cbi, const float* __restrict__ cbf,
    const float* __restrict__ cbc, const float* __restrict__ cbo,
    const float* __restrict__ bi, const float* __restrict__ bf,
    const float* __restrict__ bc, const float* __restrict__ bo)
{
    int idx = blockIdx.x * blockDim.x + threadIdx.x;
    if (idx < 73728) {
        int hh   = idx & 1;
        int r    = (idx >> 1) & 1;
        int lane = (idx >> 2) & 31;
        int t    = (idx >> 7) & 15;
        int wg   = (idx >> 11) & 3;
        int s    = idx >> 13;
        int k    = s * 16 + (lane & 3) * 2 + r * 8 + hh;    // 0..143
        int pcol = wg * 128 + t * 8 + (lane >> 2);
        int j = pcol >> 2, g = pcol & 3;
        const float* W = (g == 0) ? Wi : (g == 1) ? Wf : (g == 2) ? Wc : Wo;
        const float* C = (g == 0) ? Ci : (g == 1) ? Cf : (g == 2) ? Cc : Co;
        float v = (k < 16) ? W[k * 128 + j] : C[(k - 16) * 128 + j];
        g_Bph[idx] = __float2half_rn(v);
    } else if (idx < 73728 + 512) {
        int col = idx - 73728;
        int g = col >> 7, j = col & 127;
        const float* cb = (g == 0) ? cbi : (g == 1) ? cbf : (g == 2) ? cbc : cbo;
        const float* bb = (g == 0) ? bi  : (g == 1) ? bf  : (g == 2) ? bc  : bo;
        g_bias[col] = cb[j] + bb[j];
    }
}

// ---------------------------------------------------------------------------
// Gates kernel: 64 rows x 256 pcols per CTA (blockIdx.y = col half).
// smem (bytes):
//   sA    64 x 304B (152 halves)    @ 0        (19456)
//   sB    18432 u32 fragments       @ 19456    (73728)   [reused in epilogue:
//         sCin @19456, sHo @36864, sCo @54272, each 64x68 f = 17408 B]
//   sBias 256 f (4 gates x 64 j)    @ 93184    (1024)
//   sPeep 192 f (3 x 64 j)          @ 94208    (768)
// total 94976 B -> 2 CTAs/SM.
// ---------------------------------------------------------------------------
#define GA_SA    0
#define GA_SB    19456
#define GA_CIN   19456
#define GA_HO    36864
#define GA_CO    54272
#define GA_BIAS  93184
#define GA_PEEP  94208
#define GATES_SMEM_BYTES 94976

__global__ __launch_bounds__(256, 2)
void gates_mma(const float* __restrict__ x, const float* __restrict__ h,
               const float* __restrict__ c,
               const float* __restrict__ wci, const float* __restrict__ wcf,
               const float* __restrict__ wco,
               float* __restrict__ outh, float* __restrict__ outc, int N)
{
    extern __shared__ char sm[];
    char*  sA    = sm + GA_SA;
    const uint32_t* sBu = (const uint32_t*)(sm + GA_SB);
    float* sBias = (float*)(sm + GA_BIAS);
    float* sPeep = (float*)(sm + GA_PEEP);

    const int tid   = threadIdx.x;
    const int lane  = tid & 31;
    const int wid   = tid >> 5;
    const int warpM = wid >> 2;         // 0..1  (32-row slab)
    const int warpN = wid & 3;          // 0..3  (64-pcol slab)
    const int wgl   = warpN >> 1;       // local wg (0..1)
    const int t0    = (warpN & 1) * 8;  // n8-tile offset within wg
    const int g4    = lane >> 2;
    const int tg    = lane & 3;
    const int row0  = blockIdx.x * 64;
    const int cH    = blockIdx.y;       // col half: pcols cH*256..+255

    // ---- Stage A as fp16: 64 rows x 144 halves, stride 152 halves ---------
    #pragma unroll
    for (int ii = 0; ii < 5; ++ii) {
        int i = tid + ii * 256;
        if (i < 1152) {
            int row = i / 18, ch = i % 18;
            int grow = row0 + row; if (grow >= N) grow = N - 1;
            float4 v0, v1;
            if (ch < 2) {
                const float4* p = (const float4*)&x[(size_t)grow * 16 + ch * 8];
                v0 = p[0]; v1 = p[1];
            } else {
                const float4* p = (const float4*)&h[(size_t)grow * 128 + ch * 8 - 16];
                v0 = p[0]; v1 = p[1];
            }
            uint4 o;
            o.x = f2h2(v0.x, v0.y); o.y = f2h2(v0.z, v0.w);
            o.z = f2h2(v1.x, v1.y); o.w = f2h2(v1.z, v1.w);
            *(uint4*)(sA + row * 304 + ch * 16) = o;
        }
    }
    // ---- Stage B half: wg pair {cH*2, cH*2+1}, all s,t (72 KB) ------------
    {
        const uint4* src = (const uint4*)g_Bph;
        uint4* dst = (uint4*)(sm + GA_SB);
        #pragma unroll
        for (int ii = 0; ii < 18; ++ii) {
            int i = tid + ii * 256;                 // 0..4607 (uint4 units)
            int s = i >> 9, rem = i & 511;          // 512 uint4 per s
            dst[s * 512 + rem] = src[(s * 4 + cH * 2) * 256 + rem];
        }
    }
    // ---- Bias / peephole slices for this col half -------------------------
    {
        int g = tid >> 6, jl = tid & 63;
        sBias[tid] = g_bias[g * 128 + cH * 64 + jl];
        if (tid < 192) {
            const float* P = (g == 0) ? wci : (g == 1) ? wcf : wco;
            sPeep[tid] = P[cH * 64 + jl];
        }
    }
    __syncthreads();

    // ---- Barrier-free mma mainloop ----------------------------------------
    const int lrow = lane & 15;
    const int lkof = (lane >> 4) * 8;
    const uint32_t aBase = s2u(sA) + (uint32_t)(warpM * 32 + lrow) * 304 + lkof * 2;

    float acc[2][8][4];
    #pragma unroll
    for (int m = 0; m < 2; ++m)
        #pragma unroll
        for (int t = 0; t < 8; ++t)
            #pragma unroll
            for (int e = 0; e < 4; ++e) acc[m][t][e] = 0.f;

    #pragma unroll
    for (int s = 0; s < 9; ++s) {
        uint32_t a[2][4];
        ldm4(a[0][0], a[0][1], a[0][2], a[0][3], aBase + s * 32);
        ldm4(a[1][0], a[1][1], a[1][2], a[1][3], aBase + s * 32 + 16 * 304);
        const uint32_t* bb = sBu + ((s * 2 + wgl) * 16 + t0) * 64 + lane * 2;
        #pragma unroll
        for (int t = 0; t < 8; ++t) {
            uint32_t b0 = bb[t * 64], b1 = bb[t * 64 + 1];
            mma16(acc[0][t][0], acc[0][t][1], acc[0][t][2], acc[0][t][3],
                  a[0][0], a[0][1], a[0][2], a[0][3], b0, b1);
            mma16(acc[1][t][0], acc[1][t][1], acc[1][t][2], acc[1][t][3],
                  a[1][0], a[1][1], a[1][2], a[1][3], b0, b1);
        }
    }
    __syncthreads();   // everyone done reading sB -> safe to reuse

    // ---- Stage c coalesced: 64 rows x 64 cols (this half) -----------------
    {
        float* sCin = (float*)(sm + GA_CIN);
        #pragma unroll
        for (int ii = 0; ii < 4; ++ii) {
            int i = tid + ii * 256;                 // 0..1023
            int r = i >> 4, q = i & 15;
            int grow = row0 + r; if (grow >= N) grow = N - 1;
            float4 v = ((const float4*)c)[(size_t)grow * 32 + cH * 16 + q];
            *(float4*)((char*)sCin + (r * 68 + q * 4) * 4) = v;
        }
    }
    __syncthreads();

    // ---- Epilogue: LSTM cell math from registers + staged c ---------------
    {
        const float* sCin = (const float*)(sm + GA_CIN);
        float* sHo = (float*)(sm + GA_HO);
        float* sCo = (float*)(sm + GA_CO);
        #pragma unroll
        for (int m = 0; m < 2; ++m) {
            const int rbase = warpM * 32 + m * 16 + g4;
            #pragma unroll
            for (int t = 0; t < 8; ++t) {
                float c0 = acc[m][t][0], c1 = acc[m][t][1];
                float c2 = acc[m][t][2], c3 = acc[m][t][3];
                float o0 = __shfl_xor_sync(0xffffffffu, c0, 1);
                float o1 = __shfl_xor_sync(0xffffffffu, c1, 1);
                float o2 = __shfl_xor_sync(0xffffffffu, c2, 1);
                float o3 = __shfl_xor_sync(0xffffffffu, c3, 1);
                int jl = wgl * 32 + (t0 + t) * 2 + (tg >> 1);
                int odd = lane & 1;
                int r = odd ? rbase + 8 : rbase;
                float gi = odd ? o2 : c0;
                float gf = odd ? o3 : c1;
                float gc = odd ? c2 : o0;
                float go = odd ? c3 : o1;
                float co = sCin[r * 68 + jl];
                float pi = gi + sBias[jl]       + sPeep[jl] * co;
                float pf = gf + sBias[64 + jl]  + sPeep[64 + jl] * co;
                float pc = gc + sBias[128 + jl];
                float po = go + sBias[192 + jl];
                float iv = sigm(pi), fv = sigm(pf), tv = tanhv(pc);
                float cn = fv * co + iv * tv;
                float ov = sigm(po + sPeep[128 + jl] * cn);
                sHo[r * 68 + jl] = ov * tanhv(cn);
                sCo[r * 68 + jl] = cn;
            }
        }
    }
    __syncthreads();

    // ---- Coalesced float4 stores of h_new / c_new -------------------------
    {
        const char* sHo = sm + GA_HO;
        const char* sCo = sm + GA_CO;
        #pragma unroll
        for (int ii = 0; ii < 4; ++ii) {
            int i = tid + ii * 256;
            int r = i >> 4, q = i & 15;
            int grow = row0 + r;
            if (grow < N) {
                float4 hv = *(const float4*)(sHo + (r * 68 + q * 4) * 4);
                float4 cv = *(const float4*)(sCo + (r * 68 + q * 4) * 4);
                ((float4*)outh)[(size_t)grow * 32 + cH * 16 + q] = hv;
                ((float4*)outc)[(size_t)grow * 32 + cH * 16 + q] = cv;
            }
        }
    }
}

// ---------------------------------------------------------------------------
// MLP head: relu -> 64 -> relu -> 64 -> relu -> 1 (round-4 validated).
// ---------------------------------------------------------------------------
#define MLP_SMEM_BYTES 101120

__global__ __launch_bounds__(256)
void mlp_kernel(const float* __restrict__ hsrc,
                const float* __restrict__ w1, const float* __restrict__ b1,
                const float* __restrict__ w2, const float* __restrict__ b2,
                const float* __restrict__ w3, const float* __restrict__ b3,
                float* __restrict__ out, int N)
{
    extern __shared__ float smf[];
    float* sW1 = smf;
    float* sW2 = smf + 8192;
    float* sW3 = smf + 12288;
    float* sB1 = smf + 12352;
    float* sB2 = smf + 12416;
    float* sH  = smf + 12480;     // stride 132
    float* sL1 = smf + 20928;     // stride 68
    float* sL2 = sH;              // stride 68 (reuse)

    const int tid  = threadIdx.x;
    const int row0 = blockIdx.x * 64;

    #pragma unroll
    for (int i = 0; i < 8; ++i)
        ((float4*)sW1)[tid + i * 256] = ((const float4*)w1)[tid + i * 256];
    #pragma unroll
    for (int i = 0; i < 4; ++i)
        ((float4*)sW2)[tid + i * 256] = ((const float4*)w2)[tid + i * 256];
    if (tid < 64) { sW3[tid] = w3[tid]; sB1[tid] = b1[tid]; sB2[tid] = b2[tid]; }
    {
        int r = tid >> 2, q = tid & 3;
        int grow = row0 + r; if (grow >= N) grow = N - 1;
        #pragma unroll
        for (int i = 0; i < 8; ++i) {
            float4 v = *(const float4*)&hsrc[(size_t)grow * 128 + q * 32 + i * 4];
            v.x = fmaxf(v.x, 0.f); v.y = fmaxf(v.y, 0.f);
            v.z = fmaxf(v.z, 0.f); v.w = fmaxf(v.w, 0.f);
            *(float4*)&sH[r * 132 + q * 32 + i * 4] = v;
        }
    }
    __syncthreads();

    const int to = (tid & 15) * 4;
    const int tr = (tid >> 4) * 4;

    // Layer 1: 128 -> 64
    {
        ull ib0 = *(const ull*)&sB1[to];
        ull ib1 = *(const ull*)&sB1[to + 2];
        ull acc[4][2];
        #pragma unroll
        for (int i = 0; i < 4; ++i) { acc[i][0] = ib0; acc[i][1] = ib1; }
        #pragma unroll 4
        for (int k4 = 0; k4 < 32; ++k4) {
            ull w0[4], w1v[4];
            #pragma unroll
            for (int kk = 0; kk < 4; ++kk) {
                float4 wv = *(const float4*)&sW1[(k4 * 4 + kk) * 64 + to];
                w0[kk] = pack2(wv.x, wv.y); w1v[kk] = pack2(wv.z, wv.w);
            }
            #pragma unroll
            for (int i = 0; i < 4; ++i) {
                float4 hv = *(const float4*)&sH[(tr + i) * 132 + k4 * 4];
                float hs[4] = {hv.x, hv.y, hv.z, hv.w};
                #pragma unroll
                for (int kk = 0; kk < 4; ++kk) {
                    ull a2 = pack2(hs[kk], hs[kk]);
                    fma2(acc[i][0], a2, w0[kk]);
                    fma2(acc[i][1], a2, w1v[kk]);
                }
            }
        }
        #pragma unroll
        for (int i = 0; i < 4; ++i) {
            float v0, v1, v2, v3;
            unpack2(acc[i][0], v0, v1); unpack2(acc[i][1], v2, v3);
            *(float4*)&sL1[(tr + i) * 68 + to] =
                make_float4(fmaxf(v0, 0.f), fmaxf(v1, 0.f),
                            fmaxf(v2, 0.f), fmaxf(v3, 0.f));
        }
    }
    __syncthreads();

    // Layer 2: 64 -> 64
    {
        ull ib0 = *(const ull*)&sB2[to];
        ull ib1 = *(const ull*)&sB2[to + 2];
        ull acc[4][2];
        #pragma unroll
        for (int i = 0; i < 4; ++i) { acc[i][0] = ib0; acc[i][1] = ib1; }
        #pragma unroll 4
        for (int k4 = 0; k4 < 16; ++k4) {
            ull w0[4], w1v[4];
            #pragma unroll
            for (int kk = 0; kk < 4; ++kk) {
                float4 wv = *(const float4*)&sW2[(k4 * 4 + kk) * 64 + to];
                w0[kk] = pack2(wv.x, wv.y); w1v[kk] = pack2(wv.z, wv.w);
            }
            #pragma unroll
            for (int i = 0; i < 4; ++i) {
                float4 hv = *(const float4*)&sL1[(tr + i) * 68 + k4 * 4];
                float hs[4] = {hv.x, hv.y, hv.z, hv.w};
                #pragma unroll
                for (int kk = 0; kk < 4; ++kk) {
                    ull a2 = pack2(hs[kk], hs[kk]);
                    fma2(acc[i][0], a2, w0[kk]);
                    fma2(acc[i][1], a2, w1v[kk]);
                }
            }
        }
        __syncthreads();   // sL1 reads done before overwriting sL2 (== sH)
        #pragma unroll
        for (int i = 0; i < 4; ++i) {
            float v0, v1, v2, v3;
            unpack2(acc[i][0], v0, v1); unpack2(acc[i][1], v2, v3);
            *(float4*)&sL2[(tr + i) * 68 + to] =
                make_float4(fmaxf(v0, 0.f), fmaxf(v1, 0.f),
                            fmaxf(v2, 0.f), fmaxf(v3, 0.f));
        }
    }
    __syncthreads();

    // Layer 3: 64 -> 1
    if (tid < 64) {
        int grow = row0 + tid;
        if (grow < N) {
            float a = b3[0];
            #pragma unroll
            for (int k = 0; k < 64; ++k) a += sL2[tid * 68 + k] * sW3[k];
            out[grow] = a;
        }
    }
}

// ---------------------------------------------------------------------------
extern "C" void kernel_launch(void* const* d_in, const int* in_sizes, int n_in,
                              void* d_out, int out_size)
{
    const float* x   = (const float*)d_in[0];
    const float* h   = (const float*)d_in[3];
    const float* c   = (const float*)d_in[4];
    const float* Wi  = (const float*)d_in[5];
    const float* Wf  = (const float*)d_in[6];
    const float* Wc  = (const float*)d_in[7];
    const float* Wo  = (const float*)d_in[8];
    const float* Ci  = (const float*)d_in[9];
    const float* Cf  = (const float*)d_in[10];
    const float* Cc  = (const float*)d_in[11];
    const float* Co  = (const float*)d_in[12];
    const float* cbi = (const float*)d_in[13];
    const float* cbf = (const float*)d_in[14];
    const float* cbc = (const float*)d_in[15];
    const float* cbo = (const float*)d_in[16];
    const float* wci = (const float*)d_in[17];
    const float* wcf = (const float*)d_in[18];
    const float* wco = (const float*)d_in[19];
    const float* bi  = (const float*)d_in[20];
    const float* bf  = (const float*)d_in[21];
    const float* bc  = (const float*)d_in[22];
    const float* bo  = (const float*)d_in[23];
    const float* w1  = (const float*)d_in[24];
    const float* b1  = (const float*)d_in[25];
    const float* w2  = (const float*)d_in[26];
    const float* b2  = (const float*)d_in[27];
    const float* w3  = (const float*)d_in[28];
    const float* b3  = (const float*)d_in[29];

    const int N = in_sizes[3] / 128;

    float* out  = (float*)d_out;
    float* outh = out + N;
    float* outc = outh + (size_t)N * 128;

    pack_kernel<<<(73728 + 512 + 255) / 256, 256>>>(
        Wi, Wf, Wc, Wo, Ci, Cf, Cc, Co,
        cbi, cbf, cbc, cbo, bi, bf, bc, bo);

    cudaFuncSetAttribute(gates_mma,
                         cudaFuncAttributeMaxDynamicSharedMemorySize,
                         GATES_SMEM_BYTES);
    dim3 ggrid((N + 63) / 64, 2);
    gates_mma<<<ggrid, 256, GATES_SMEM_BYTES>>>(
        x, h, c, wci, wcf, wco, outh, outc, N);

    cudaFuncSetAttribute(mlp_kernel,
                         cudaFuncAttributeMaxDynamicSharedMemorySize,
                         MLP_SMEM_BYTES);
    mlp_kernel<<<(N + 63) / 64, 256, MLP_SMEM_BYTES>>>(
        outh, w1, b1, w2, b2, w3, b3, out, N);
}

// round 7
// speedup vs baseline: 4.0766x; 1.6506x over previous
#include <cuda_runtime.h>
#include <cuda_fp16.h>
#include <cstdint>

// ---------------------------------------------------------------------------
// RecurrentGCN (GCLSTM + MLP head).
// Gates: fp16 mma.sync m16n8k16, 64x256 CTA tiles, 2 CTAs/SM, col-half-major
//        grid (h L2 reuse), c prefetched into regs, smem-staged epilogue.
// MLP:   fp16 mma.sync for layers 1-2, scalar layer 3.
// d_out: out[N] | h_new[N,128] | c_new[N,128]
// ---------------------------------------------------------------------------

typedef unsigned long long ull;

// Gates B packed fragment-major fp16 (validated R4):
// half idx = ((((s*4+wg)*16+t)*64) + lane*2 + r)*2 + hh
//   k = s*16+(lane&3)*2+r*8+hh; pcol = wg*128 + t*8 + (lane>>2); g=pcol&3,j=pcol>>2
__device__ __half g_Bph[73728];
__device__ float  g_bias[512];          // [g*128+j] = conv_g_b[j] + b_g[j]
// MLP weight fragments fp16: same frag layout, 1 "gate", t over 8 n8-tiles.
__device__ __half g_W1f[8192];          // [s8][t8][lane32][r2][hh2], k=s*16+...
__device__ __half g_W2f[4096];          // [s4][t8][lane32][r2][hh2]

// ---------------- helpers --------------------------------------------------
__device__ __forceinline__ uint32_t s2u(const void* p) {
    uint32_t a;
    asm("{ .reg .u64 t; cvta.to.shared.u64 t, %1; cvt.u32.u64 %0, t; }"
        : "=r"(a) : "l"(p));
    return a;
}
__device__ __forceinline__ void mma16(float& d0, float& d1, float& d2, float& d3,
                                      uint32_t a0, uint32_t a1, uint32_t a2,
                                      uint32_t a3, uint32_t b0, uint32_t b1) {
    asm volatile(
        "mma.sync.aligned.m16n8k16.row.col.f32.f16.f16.f32 "
        "{%0,%1,%2,%3},{%4,%5,%6,%7},{%8,%9},{%0,%1,%2,%3};"
        : "+f"(d0), "+f"(d1), "+f"(d2), "+f"(d3)
        : "r"(a0), "r"(a1), "r"(a2), "r"(a3), "r"(b0), "r"(b1));
}
__device__ __forceinline__ void ldm4(uint32_t& r0, uint32_t& r1, uint32_t& r2,
                                     uint32_t& r3, uint32_t addr) {
    asm volatile("ldmatrix.sync.aligned.m8n8.x4.shared.b16 {%0,%1,%2,%3}, [%4];"
                 : "=r"(r0), "=r"(r1), "=r"(r2), "=r"(r3) : "r"(addr));
}
__device__ __forceinline__ float sigm(float v) {
    return __fdividef(1.f, 1.f + __expf(-v));
}
__device__ __forceinline__ float tanhv(float v) {
    v = fminf(fmaxf(v, -20.f), 20.f);
    float e = __expf(-2.f * v);
    return __fdividef(1.f - e, 1.f + e);
}
__device__ __forceinline__ uint32_t f2h2(float a, float b) {
    __half2 h = __floats2half2_rn(a, b);
    return *(uint32_t*)&h;
}

// ---------------------------------------------------------------------------
// Pack kernel: gates B frags + fused bias + MLP W1/W2 frags.
// ---------------------------------------------------------------------------
__global__ void pack_kernel(
    const float* __restrict__ Wi, const float* __restrict__ Wf,
    const float* __restrict__ Wc, const float* __restrict__ Wo,
    const float* __restrict__ Ci, const float* __restrict__ Cf,
    const float* __restrict__ Cc, const float* __restrict__ Co,
    const float* __restrict__ cbi, const float* __restrict__ cbf,
    const float* __restrict__ cbc, const float* __restrict__ cbo,
    const float* __restrict__ bi, const float* __restrict__ bf,
    const float* __restrict__ bc, const float* __restrict__ bo,
    const float* __restrict__ w1, const float* __restrict__ w2)
{
    int idx = blockIdx.x * blockDim.x + threadIdx.x;
    if (idx < 73728) {
        int hh   = idx & 1;
        int r    = (idx >> 1) & 1;
        int lane = (idx >> 2) & 31;
        int t    = (idx >> 7) & 15;
        int wg   = (idx >> 11) & 3;
        int s    = idx >> 13;
        int k    = s * 16 + (lane & 3) * 2 + r * 8 + hh;
        int pcol = wg * 128 + t * 8 + (lane >> 2);
        int j = pcol >> 2, g = pcol & 3;
        const float* W = (g == 0) ? Wi : (g == 1) ? Wf : (g == 2) ? Wc : Wo;
        const float* C = (g == 0) ? Ci : (g == 1) ? Cf : (g == 2) ? Cc : Co;
        float v = (k < 16) ? W[k * 128 + j] : C[(k - 16) * 128 + j];
        g_Bph[idx] = __float2half_rn(v);
    } else if (idx < 74240) {
        int col = idx - 73728;
        int g = col >> 7, j = col & 127;
        const float* cb = (g == 0) ? cbi : (g == 1) ? cbf : (g == 2) ? cbc : cbo;
        const float* bb = (g == 0) ? bi  : (g == 1) ? bf  : (g == 2) ? bc  : bo;
        g_bias[col] = cb[j] + bb[j];
    } else if (idx < 74240 + 8192) {
        int i = idx - 74240;
        int hh = i & 1, r = (i >> 1) & 1, lane = (i >> 2) & 31;
        int t = (i >> 7) & 7, s = (i >> 10) & 7;
        int k = s * 16 + (lane & 3) * 2 + r * 8 + hh;
        int col = t * 8 + (lane >> 2);
        g_W1f[i] = __float2half_rn(w1[k * 64 + col]);
    } else if (idx < 74240 + 8192 + 4096) {
        int i = idx - 74240 - 8192;
        int hh = i & 1, r = (i >> 1) & 1, lane = (i >> 2) & 31;
        int t = (i >> 7) & 7, s = (i >> 10) & 3;
        int k = s * 16 + (lane & 3) * 2 + r * 8 + hh;
        int col = t * 8 + (lane >> 2);
        g_W2f[i] = __float2half_rn(w2[k * 64 + col]);
    }
}

// ---------------------------------------------------------------------------
// Gates kernel: 64 rows x 256 pcols per CTA; blockIdx.x = col half (adjacent
// bids share the h row-slab -> L2 hit), blockIdx.y = row slab.
// smem map identical to round 5.
// ---------------------------------------------------------------------------
#define GA_SA    0
#define GA_SB    19456
#define GA_CIN   19456
#define GA_HO    36864
#define GA_CO    54272
#define GA_BIAS  93184
#define GA_PEEP  94208
#define GATES_SMEM_BYTES 94976

__global__ __launch_bounds__(256, 2)
void gates_mma(const float* __restrict__ x, const float* __restrict__ h,
               const float* __restrict__ c,
               const float* __restrict__ wci, const float* __restrict__ wcf,
               const float* __restrict__ wco,
               float* __restrict__ outh, float* __restrict__ outc, int N)
{
    extern __shared__ char sm[];
    char*  sA    = sm + GA_SA;
    const uint32_t* sBu = (const uint32_t*)(sm + GA_SB);
    float* sBias = (float*)(sm + GA_BIAS);
    float* sPeep = (float*)(sm + GA_PEEP);

    const int tid   = threadIdx.x;
    const int lane  = tid & 31;
    const int wid   = tid >> 5;
    const int warpM = wid >> 2;
    const int warpN = wid & 3;
    const int wgl   = warpN >> 1;
    const int t0    = (warpN & 1) * 8;
    const int g4    = lane >> 2;
    const int tg    = lane & 3;
    const int cH    = blockIdx.x;            // col half
    const int row0  = blockIdx.y * 64;       // row slab

    // ---- Prefetch c (coalesced float4) into registers ---------------------
    float4 cpre[4];
    #pragma unroll
    for (int ii = 0; ii < 4; ++ii) {
        int i = tid + ii * 256;
        int r = i >> 4, q = i & 15;
        int grow = row0 + r; if (grow >= N) grow = N - 1;
        cpre[ii] = ((const float4*)c)[(size_t)grow * 32 + cH * 16 + q];
    }

    // ---- Stage A as fp16: 64 rows x 144 halves, stride 152 halves ---------
    #pragma unroll
    for (int ii = 0; ii < 5; ++ii) {
        int i = tid + ii * 256;
        if (i < 1152) {
            int row = i / 18, ch = i % 18;
            int grow = row0 + row; if (grow >= N) grow = N - 1;
            float4 v0, v1;
            if (ch < 2) {
                const float4* p = (const float4*)&x[(size_t)grow * 16 + ch * 8];
                v0 = p[0]; v1 = p[1];
            } else {
                const float4* p = (const float4*)&h[(size_t)grow * 128 + ch * 8 - 16];
                v0 = p[0]; v1 = p[1];
            }
            uint4 o;
            o.x = f2h2(v0.x, v0.y); o.y = f2h2(v0.z, v0.w);
            o.z = f2h2(v1.x, v1.y); o.w = f2h2(v1.z, v1.w);
            *(uint4*)(sA + row * 304 + ch * 16) = o;
        }
    }
    // ---- Stage B half: wg pair {cH*2, cH*2+1} (72 KB) ---------------------
    {
        const uint4* src = (const uint4*)g_Bph;
        uint4* dst = (uint4*)(sm + GA_SB);
        #pragma unroll
        for (int ii = 0; ii < 18; ++ii) {
            int i = tid + ii * 256;
            int s = i >> 9, rem = i & 511;
            dst[s * 512 + rem] = src[(s * 4 + cH * 2) * 256 + rem];
        }
    }
    {
        int g = tid >> 6, jl = tid & 63;
        sBias[tid] = g_bias[g * 128 + cH * 64 + jl];
        if (tid < 192) {
            const float* P = (g == 0) ? wci : (g == 1) ? wcf : wco;
            sPeep[tid] = P[cH * 64 + jl];
        }
    }
    __syncthreads();

    // ---- Barrier-free mma mainloop ----------------------------------------
    const int lrow = lane & 15;
    const int lkof = (lane >> 4) * 8;
    const uint32_t aBase = s2u(sA) + (uint32_t)(warpM * 32 + lrow) * 304 + lkof * 2;

    float acc[2][8][4];
    #pragma unroll
    for (int m = 0; m < 2; ++m)
        #pragma unroll
        for (int t = 0; t < 8; ++t)
            #pragma unroll
            for (int e = 0; e < 4; ++e) acc[m][t][e] = 0.f;

    #pragma unroll
    for (int s = 0; s < 9; ++s) {
        uint32_t a[2][4];
        ldm4(a[0][0], a[0][1], a[0][2], a[0][3], aBase + s * 32);
        ldm4(a[1][0], a[1][1], a[1][2], a[1][3], aBase + s * 32 + 16 * 304);
        const uint32_t* bb = sBu + ((s * 2 + wgl) * 16 + t0) * 64 + lane * 2;
        #pragma unroll
        for (int t = 0; t < 8; ++t) {
            uint32_t b0 = bb[t * 64], b1 = bb[t * 64 + 1];
            mma16(acc[0][t][0], acc[0][t][1], acc[0][t][2], acc[0][t][3],
                  a[0][0], a[0][1], a[0][2], a[0][3], b0, b1);
            mma16(acc[1][t][0], acc[1][t][1], acc[1][t][2], acc[1][t][3],
                  a[1][0], a[1][1], a[1][2], a[1][3], b0, b1);
        }
    }
    __syncthreads();   // done reading sB -> reuse region

    // ---- Store prefetched c -----------------------------------------------
    {
        float* sCin = (float*)(sm + GA_CIN);
        #pragma unroll
        for (int ii = 0; ii < 4; ++ii) {
            int i = tid + ii * 256;
            int r = i >> 4, q = i & 15;
            *(float4*)((char*)sCin + (r * 68 + q * 4) * 4) = cpre[ii];
        }
    }
    __syncthreads();

    // ---- Epilogue: LSTM cell math -----------------------------------------
    {
        const float* sCin = (const float*)(sm + GA_CIN);
        float* sHo = (float*)(sm + GA_HO);
        float* sCo = (float*)(sm + GA_CO);
        #pragma unroll
        for (int m = 0; m < 2; ++m) {
            const int rbase = warpM * 32 + m * 16 + g4;
            #pragma unroll
            for (int t = 0; t < 8; ++t) {
                float c0 = acc[m][t][0], c1 = acc[m][t][1];
                float c2 = acc[m][t][2], c3 = acc[m][t][3];
                float o0 = __shfl_xor_sync(0xffffffffu, c0, 1);
                float o1 = __shfl_xor_sync(0xffffffffu, c1, 1);
                float o2 = __shfl_xor_sync(0xffffffffu, c2, 1);
                float o3 = __shfl_xor_sync(0xffffffffu, c3, 1);
                int jl = wgl * 32 + (t0 + t) * 2 + (tg >> 1);
                int odd = lane & 1;
                int r = odd ? rbase + 8 : rbase;
                float gi = odd ? o2 : c0;
                float gf = odd ? o3 : c1;
                float gc = odd ? c2 : o0;
                float go = odd ? c3 : o1;
                float co = sCin[r * 68 + jl];
                float pi = gi + sBias[jl]       + sPeep[jl] * co;
                float pf = gf + sBias[64 + jl]  + sPeep[64 + jl] * co;
                float pc = gc + sBias[128 + jl];
                float po = go + sBias[192 + jl];
                float iv = sigm(pi), fv = sigm(pf), tv = tanhv(pc);
                float cn = fv * co + iv * tv;
                float ov = sigm(po + sPeep[128 + jl] * cn);
                sHo[r * 68 + jl] = ov * tanhv(cn);
                sCo[r * 68 + jl] = cn;
            }
        }
    }
    __syncthreads();

    // ---- Coalesced float4 stores ------------------------------------------
    {
        const char* sHo = sm + GA_HO;
        const char* sCo = sm + GA_CO;
        #pragma unroll
        for (int ii = 0; ii < 4; ++ii) {
            int i = tid + ii * 256;
            int r = i >> 4, q = i & 15;
            int grow = row0 + r;
            if (grow < N) {
                float4 hv = *(const float4*)(sHo + (r * 68 + q * 4) * 4);
                float4 cv = *(const float4*)(sCo + (r * 68 + q * 4) * 4);
                ((float4*)outh)[(size_t)grow * 32 + cH * 16 + q] = hv;
                ((float4*)outc)[(size_t)grow * 32 + cH * 16 + q] = cv;
            }
        }
    }
}

// ---------------------------------------------------------------------------
// MLP head on fp16 mma: relu(h)->64 (8 k-steps) -> relu ->64 (4 k-steps)
// -> relu -> 1 (scalar dot). 64 rows/CTA, 256 threads (8 warps).
// smem (bytes):
//   sA1  64 x 272B (136 halves)  @ 0       (17408)
//   sW1f 16384                   @ 17408
//   sW2f 8192                    @ 33792
//   sA2  64 x 144B (72 halves)   @ 41984   (9216)
//   sL2  64 x 68 f               @ 51200   (17408)
//   sB1/sB2/sW3 64 f each        @ 68608   (768)
// total 69376
// ---------------------------------------------------------------------------
#define ML_A1   0
#define ML_W1F  17408
#define ML_W2F  33792
#define ML_A2   41984
#define ML_L2   51200
#define ML_SB   68608
#define MLP_SMEM_BYTES 69376

__global__ __launch_bounds__(256)
void mlp_mma(const float* __restrict__ hsrc,
             const float* __restrict__ b1, const float* __restrict__ b2,
             const float* __restrict__ w3, const float* __restrict__ b3,
             float* __restrict__ out, int N)
{
    extern __shared__ char sm[];
    char* sA1 = sm + ML_A1;
    const uint32_t* sW1u = (const uint32_t*)(sm + ML_W1F);
    const uint32_t* sW2u = (const uint32_t*)(sm + ML_W2F);
    char* sA2 = sm + ML_A2;
    float* sL2 = (float*)(sm + ML_L2);
    float* sB1 = (float*)(sm + ML_SB);
    float* sB2 = sB1 + 64;
    float* sW3 = sB1 + 128;

    const int tid   = threadIdx.x;
    const int lane  = tid & 31;
    const int wid   = tid >> 5;
    const int warpM = wid >> 2;          // 0..1 (32-row slab)
    const int warpN = wid & 3;           // 0..3 (2 n8-tiles each)
    const int g4    = lane >> 2;
    const int tg    = lane & 3;
    const int row0  = blockIdx.x * 64;

    // ---- Stage A1 = relu(h) fp16, stride 136 halves -----------------------
    #pragma unroll
    for (int ii = 0; ii < 4; ++ii) {
        int i = tid + ii * 256;          // 0..1023
        int row = i >> 4, ch = i & 15;
        int grow = row0 + row; if (grow >= N) grow = N - 1;
        const float4* p = (const float4*)&hsrc[(size_t)grow * 128 + ch * 8];
        float4 v0 = p[0], v1 = p[1];
        v0.x = fmaxf(v0.x, 0.f); v0.y = fmaxf(v0.y, 0.f);
        v0.z = fmaxf(v0.z, 0.f); v0.w = fmaxf(v0.w, 0.f);
        v1.x = fmaxf(v1.x, 0.f); v1.y = fmaxf(v1.y, 0.f);
        v1.z = fmaxf(v1.z, 0.f); v1.w = fmaxf(v1.w, 0.f);
        uint4 o;
        o.x = f2h2(v0.x, v0.y); o.y = f2h2(v0.z, v0.w);
        o.z = f2h2(v1.x, v1.y); o.w = f2h2(v1.z, v1.w);
        *(uint4*)(sA1 + row * 272 + ch * 16) = o;
    }
    // ---- Stage weight fragments + small vectors ---------------------------
    {
        const uint4* s1 = (const uint4*)g_W1f;
        uint4* d1 = (uint4*)(sm + ML_W1F);
        #pragma unroll
        for (int ii = 0; ii < 4; ++ii) d1[tid + ii * 256] = s1[tid + ii * 256];
        const uint4* s2 = (const uint4*)g_W2f;
        uint4* d2 = (uint4*)(sm + ML_W2F);
        #pragma unroll
        for (int ii = 0; ii < 2; ++ii) d2[tid + ii * 256] = s2[tid + ii * 256];
    }
    if (tid < 64) { sB1[tid] = b1[tid]; sB2[tid] = b2[tid]; sW3[tid] = w3[tid]; }
    __syncthreads();

    const int lrow = lane & 15;
    const int lkof = (lane >> 4) * 8;

    // ---- Layer 1: 128 -> 64 (8 k-steps) -----------------------------------
    {
        const uint32_t aB = s2u(sA1) + (uint32_t)(warpM * 32 + lrow) * 272 + lkof * 2;
        float acc[2][2][4];
        #pragma unroll
        for (int m = 0; m < 2; ++m)
            #pragma unroll
            for (int t = 0; t < 2; ++t)
                #pragma unroll
                for (int e = 0; e < 4; ++e) acc[m][t][e] = 0.f;
        #pragma unroll
        for (int s = 0; s < 8; ++s) {
            uint32_t a[2][4];
            ldm4(a[0][0], a[0][1], a[0][2], a[0][3], aB + s * 32);
            ldm4(a[1][0], a[1][1], a[1][2], a[1][3], aB + s * 32 + 16 * 272);
            #pragma unroll
            for (int t = 0; t < 2; ++t) {
                const uint32_t* bb = sW1u + ((s * 8 + warpN * 2 + t) * 32 + lane) * 2;
                uint32_t b0 = bb[0], b1v = bb[1];
                mma16(acc[0][t][0], acc[0][t][1], acc[0][t][2], acc[0][t][3],
                      a[0][0], a[0][1], a[0][2], a[0][3], b0, b1v);
                mma16(acc[1][t][0], acc[1][t][1], acc[1][t][2], acc[1][t][3],
                      a[1][0], a[1][1], a[1][2], a[1][3], b0, b1v);
            }
        }
        // epilogue -> relu -> fp16 -> sA2 (stride 72 halves)
        #pragma unroll
        for (int t = 0; t < 2; ++t) {
            int col = (warpN * 2 + t) * 8 + tg * 2;
            float ba = sB1[col], bb2 = sB1[col + 1];
            #pragma unroll
            for (int m = 0; m < 2; ++m) {
                int r = warpM * 32 + m * 16 + g4;
                float v0 = fmaxf(acc[m][t][0] + ba, 0.f);
                float v1 = fmaxf(acc[m][t][1] + bb2, 0.f);
                float v2 = fmaxf(acc[m][t][2] + ba, 0.f);
                float v3 = fmaxf(acc[m][t][3] + bb2, 0.f);
                *(uint32_t*)(sA2 + r * 144 + col * 2) = f2h2(v0, v1);
                *(uint32_t*)(sA2 + (r + 8) * 144 + col * 2) = f2h2(v2, v3);
            }
        }
    }
    __syncthreads();

    // ---- Layer 2: 64 -> 64 (4 k-steps) ------------------------------------
    {
        const uint32_t aB = s2u(sA2) + (uint32_t)(warpM * 32 + lrow) * 144 + lkof * 2;
        float acc[2][2][4];
        #pragma unroll
        for (int m = 0; m < 2; ++m)
            #pragma unroll
            for (int t = 0; t < 2; ++t)
                #pragma unroll
                for (int e = 0; e < 4; ++e) acc[m][t][e] = 0.f;
        #pragma unroll
        for (int s = 0; s < 4; ++s) {
            uint32_t a[2][4];
            ldm4(a[0][0], a[0][1], a[0][2], a[0][3], aB + s * 32);
            ldm4(a[1][0], a[1][1], a[1][2], a[1][3], aB + s * 32 + 16 * 144);
            #pragma unroll
            for (int t = 0; t < 2; ++t) {
                const uint32_t* bb = sW2u + ((s * 8 + warpN * 2 + t) * 32 + lane) * 2;
                uint32_t b0 = bb[0], b1v = bb[1];
                mma16(acc[0][t][0], acc[0][t][1], acc[0][t][2], acc[0][t][3],
                      a[0][0], a[0][1], a[0][2], a[0][3], b0, b1v);
                mma16(acc[1][t][0], acc[1][t][1], acc[1][t][2], acc[1][t][3],
                      a[1][0], a[1][1], a[1][2], a[1][3], b0, b1v);
            }
        }
        // epilogue -> relu -> f32 -> sL2 (stride 68)
        #pragma unroll
        for (int t = 0; t < 2; ++t) {
            int col = (warpN * 2 + t) * 8 + tg * 2;
            float ba = sB2[col], bb2 = sB2[col + 1];
            #pragma unroll
            for (int m = 0; m < 2; ++m) {
                int r = warpM * 32 + m * 16 + g4;
                *(float2*)&sL2[r * 68 + col] =
                    make_float2(fmaxf(acc[m][t][0] + ba, 0.f),
                                fmaxf(acc[m][t][1] + bb2, 0.f));
                *(float2*)&sL2[(r + 8) * 68 + col] =
                    make_float2(fmaxf(acc[m][t][2] + ba, 0.f),
                                fmaxf(acc[m][t][3] + bb2, 0.f));
            }
        }
    }
    __syncthreads();

    // ---- Layer 3: 64 -> 1 --------------------------------------------------
    if (tid < 64) {
        int grow = row0 + tid;
        if (grow < N) {
            float a = b3[0];
            #pragma unroll
            for (int k = 0; k < 64; ++k) a += sL2[tid * 68 + k] * sW3[k];
            out[grow] = a;
        }
    }
}

// ---------------------------------------------------------------------------
extern "C" void kernel_launch(void* const* d_in, const int* in_sizes, int n_in,
                              void* d_out, int out_size)
{
    const float* x   = (const float*)d_in[0];
    const float* h   = (const float*)d_in[3];
    const float* c   = (const float*)d_in[4];
    const float* Wi  = (const float*)d_in[5];
    const float* Wf  = (const float*)d_in[6];
    const float* Wc  = (const float*)d_in[7];
    const float* Wo  = (const float*)d_in[8];
    const float* Ci  = (const float*)d_in[9];
    const float* Cf  = (const float*)d_in[10];
    const float* Cc  = (const float*)d_in[11];
    const float* Co  = (const float*)d_in[12];
    const float* cbi = (const float*)d_in[13];
    const float* cbf = (const float*)d_in[14];
    const float* cbc = (const float*)d_in[15];
    const float* cbo = (const float*)d_in[16];
    const float* wci = (const float*)d_in[17];
    const float* wcf = (const float*)d_in[18];
    const float* wco = (const float*)d_in[19];
    const float* bi  = (const float*)d_in[20];
    const float* bf  = (const float*)d_in[21];
    const float* bc  = (const float*)d_in[22];
    const float* bo  = (const float*)d_in[23];
    const float* w1  = (const float*)d_in[24];
    const float* b1  = (const float*)d_in[25];
    const float* w2  = (const float*)d_in[26];
    const float* b2  = (const float*)d_in[27];
    const float* w3  = (const float*)d_in[28];
    const float* b3  = (const float*)d_in[29];

    const int N = in_sizes[3] / 128;

    float* out  = (float*)d_out;
    float* outh = out + N;
    float* outc = outh + (size_t)N * 128;

    pack_kernel<<<(74240 + 8192 + 4096 + 255) / 256, 256>>>(
        Wi, Wf, Wc, Wo, Ci, Cf, Cc, Co,
        cbi, cbf, cbc, cbo, bi, bf, bc, bo, w1, w2);

    cudaFuncSetAttribute(gates_mma,
                         cudaFuncAttributeMaxDynamicSharedMemorySize,
                         GATES_SMEM_BYTES);
    dim3 ggrid(2, (N + 63) / 64);
    gates_mma<<<ggrid, 256, GATES_SMEM_BYTES>>>(
        x, h, c, wci, wcf, wco, outh, outc, N);

    cudaFuncSetAttribute(mlp_mma,
                         cudaFuncAttributeMaxDynamicSharedMemorySize,
                         MLP_SMEM_BYTES);
    mlp_mma<<<(N + 63) / 64, 256, MLP_SMEM_BYTES>>>(
        outh, b1, b2, w3, b3, out, N);
}

// round 8
// speedup vs baseline: 4.4194x; 1.0841x over previous
#include <cuda_runtime.h>
#include <cuda_fp16.h>
#include <cstdint>

// ---------------------------------------------------------------------------
// RecurrentGCN (GCLSTM + MLP head).
// Gates: persistent fp16 mma kernel, 2 CTAs/SM, B resident in smem across all
//        row slabs, double-buffered A, in-place single-buffer epilogue.
// MLP:   fp16 mma.sync layers 1-2, scalar layer 3 (round-7 validated).
// d_out: out[N] | h_new[N,128] | c_new[N,128]
// ---------------------------------------------------------------------------

typedef unsigned long long ull;

// Gates B packed fragment-major fp16 (validated R4):
// half idx = ((((s*4+wg)*16+t)*64) + lane*2 + r)*2 + hh
__device__ __half g_Bph[73728];
__device__ float  g_bias[512];
__device__ __half g_W1f[8192];
__device__ __half g_W2f[4096];

// ---------------- helpers --------------------------------------------------
__device__ __forceinline__ uint32_t s2u(const void* p) {
    uint32_t a;
    asm("{ .reg .u64 t; cvta.to.shared.u64 t, %1; cvt.u32.u64 %0, t; }"
        : "=r"(a) : "l"(p));
    return a;
}
__device__ __forceinline__ void mma16(float& d0, float& d1, float& d2, float& d3,
                                      uint32_t a0, uint32_t a1, uint32_t a2,
                                      uint32_t a3, uint32_t b0, uint32_t b1) {
    asm volatile(
        "mma.sync.aligned.m16n8k16.row.col.f32.f16.f16.f32 "
        "{%0,%1,%2,%3},{%4,%5,%6,%7},{%8,%9},{%0,%1,%2,%3};"
        : "+f"(d0), "+f"(d1), "+f"(d2), "+f"(d3)
        : "r"(a0), "r"(a1), "r"(a2), "r"(a3), "r"(b0), "r"(b1));
}
__device__ __forceinline__ void ldm4(uint32_t& r0, uint32_t& r1, uint32_t& r2,
                                     uint32_t& r3, uint32_t addr) {
    asm volatile("ldmatrix.sync.aligned.m8n8.x4.shared.b16 {%0,%1,%2,%3}, [%4];"
                 : "=r"(r0), "=r"(r1), "=r"(r2), "=r"(r3) : "r"(addr));
}
__device__ __forceinline__ float sigm(float v) {
    return __fdividef(1.f, 1.f + __expf(-v));
}
__device__ __forceinline__ float tanhv(float v) {
    v = fminf(fmaxf(v, -20.f), 20.f);
    float e = __expf(-2.f * v);
    return __fdividef(1.f - e, 1.f + e);
}
__device__ __forceinline__ uint32_t f2h2(float a, float b) {
    __half2 h = __floats2half2_rn(a, b);
    return *(uint32_t*)&h;
}

// ---------------------------------------------------------------------------
// Pack kernel (round-7 validated).
// ---------------------------------------------------------------------------
__global__ void pack_kernel(
    const float* __restrict__ Wi, const float* __restrict__ Wf,
    const float* __restrict__ Wc, const float* __restrict__ Wo,
    const float* __restrict__ Ci, const float* __restrict__ Cf,
    const float* __restrict__ Cc, const float* __restrict__ Co,
    const float* __restrict__ cbi, const float* __restrict__ cbf,
    const float* __restrict__ cbc, const float* __restrict__ cbo,
    const float* __restrict__ bi, const float* __restrict__ bf,
    const float* __restrict__ bc, const float* __restrict__ bo,
    const float* __restrict__ w1, const float* __restrict__ w2)
{
    int idx = blockIdx.x * blockDim.x + threadIdx.x;
    if (idx < 73728) {
        int hh   = idx & 1;
        int r    = (idx >> 1) & 1;
        int lane = (idx >> 2) & 31;
        int t    = (idx >> 7) & 15;
        int wg   = (idx >> 11) & 3;
        int s    = idx >> 13;
        int k    = s * 16 + (lane & 3) * 2 + r * 8 + hh;
        int pcol = wg * 128 + t * 8 + (lane >> 2);
        int j = pcol >> 2, g = pcol & 3;
        const float* W = (g == 0) ? Wi : (g == 1) ? Wf : (g == 2) ? Wc : Wo;
        const float* C = (g == 0) ? Ci : (g == 1) ? Cf : (g == 2) ? Cc : Co;
        float v = (k < 16) ? W[k * 128 + j] : C[(k - 16) * 128 + j];
        g_Bph[idx] = __float2half_rn(v);
    } else if (idx < 74240) {
        int col = idx - 73728;
        int g = col >> 7, j = col & 127;
        const float* cb = (g == 0) ? cbi : (g == 1) ? cbf : (g == 2) ? cbc : cbo;
        const float* bb = (g == 0) ? bi  : (g == 1) ? bf  : (g == 2) ? bc  : bo;
        g_bias[col] = cb[j] + bb[j];
    } else if (idx < 74240 + 8192) {
        int i = idx - 74240;
        int hh = i & 1, r = (i >> 1) & 1, lane = (i >> 2) & 31;
        int t = (i >> 7) & 7, s = (i >> 10) & 7;
        int k = s * 16 + (lane & 3) * 2 + r * 8 + hh;
        int col = t * 8 + (lane >> 2);
        g_W1f[i] = __float2half_rn(w1[k * 64 + col]);
    } else if (idx < 74240 + 8192 + 4096) {
        int i = idx - 74240 - 8192;
        int hh = i & 1, r = (i >> 1) & 1, lane = (i >> 2) & 31;
        int t = (i >> 7) & 7, s = (i >> 10) & 3;
        int k = s * 16 + (lane & 3) * 2 + r * 8 + hh;
        int col = t * 8 + (lane >> 2);
        g_W2f[i] = __float2half_rn(w2[k * 64 + col]);
    }
}

// ---------------------------------------------------------------------------
// Persistent gates kernel. smem (bytes):
//   sA0 @0 (19456), sA1 @19456 (19456)   -- double-buffered A (64 x 152h)
//   sB  @38912 (73728)                   -- resident B half
//   sBias @112640 (1024), sPeep @113664 (768).  Total 114432.
// Epilogue buffer (64 x 68 f = 17408 B) lives in the retiring A buffer.
// ---------------------------------------------------------------------------
#define GA_A0    0
#define GA_A1    19456
#define GA_SB    38912
#define GA_BIAS  112640
#define GA_PEEP  113664
#define GATES_SMEM_BYTES 114432

__device__ __forceinline__ void stageA(char* dst, const float4* x4,
                                       const float4* h4, int row0, int N,
                                       int tid) {
    #pragma unroll
    for (int ii = 0; ii < 5; ++ii) {
        int i = tid + ii * 256;
        if (i < 1152) {
            int row = i / 18, ch = i % 18;
            int grow = row0 + row; if (grow >= N) grow = N - 1;
            float4 v0, v1;
            if (ch < 2) {
                v0 = x4[(size_t)grow * 4 + ch * 2];
                v1 = x4[(size_t)grow * 4 + ch * 2 + 1];
            } else {
                v0 = h4[(size_t)grow * 32 + ch * 2 - 4];
                v1 = h4[(size_t)grow * 32 + ch * 2 - 3];
            }
            uint4 o;
            o.x = f2h2(v0.x, v0.y); o.y = f2h2(v0.z, v0.w);
            o.z = f2h2(v1.x, v1.y); o.w = f2h2(v1.z, v1.w);
            *(uint4*)(dst + row * 304 + ch * 16) = o;
        }
    }
}

__global__ __launch_bounds__(256, 2)
void gates_mma(const float* __restrict__ x, const float* __restrict__ h,
               const float* __restrict__ c,
               const float* __restrict__ wci, const float* __restrict__ wcf,
               const float* __restrict__ wco,
               float* __restrict__ outh, float* __restrict__ outc,
               int N, int nSlab)
{
    extern __shared__ char sm[];
    const uint32_t* sBu = (const uint32_t*)(sm + GA_SB);
    float* sBias = (float*)(sm + GA_BIAS);
    float* sPeep = (float*)(sm + GA_PEEP);

    const int tid   = threadIdx.x;
    const int lane  = tid & 31;
    const int wid   = tid >> 5;
    const int warpM = wid >> 2;
    const int warpN = wid & 3;
    const int wgl   = warpN >> 1;
    const int t0    = (warpN & 1) * 8;
    const int g4    = lane >> 2;
    const int tg    = lane & 3;
    const int cH    = blockIdx.x & 1;
    const int slab0 = blockIdx.x >> 1;

    const float4* x4 = (const float4*)x;
    const float4* h4 = (const float4*)h;

    // ---- One-time: B half, bias, peepholes --------------------------------
    {
        const uint4* src = (const uint4*)g_Bph;
        uint4* dst = (uint4*)(sm + GA_SB);
        #pragma unroll
        for (int ii = 0; ii < 18; ++ii) {
            int i = tid + ii * 256;
            int s = i >> 9, rem = i & 511;
            dst[s * 512 + rem] = src[(s * 4 + cH * 2) * 256 + rem];
        }
        int g = tid >> 6, jl = tid & 63;
        sBias[tid] = g_bias[g * 128 + cH * 64 + jl];
        if (tid < 192) {
            const float* P = (g == 0) ? wci : (g == 1) ? wcf : wco;
            sPeep[tid] = P[cH * 64 + jl];
        }
    }
    if (slab0 >= nSlab) return;

    // Stage A for first slab into buffer 0.
    stageA(sm + GA_A0, x4, h4, slab0 * 64, N, tid);
    __syncthreads();

    const int lrow = lane & 15;
    const int lkof = (lane >> 4) * 8;
    const uint32_t aOff = (uint32_t)(warpM * 32 + lrow) * 304 + lkof * 2;
    const uint32_t aB0 = s2u(sm + GA_A0) + aOff;
    const uint32_t aB1 = s2u(sm + GA_A1) + aOff;

    int buf = 0;
    for (int sl = slab0; sl < nSlab; sl += 148, buf ^= 1) {
        const int row0 = sl * 64;

        // ---- Prefetch c for this slab (latency hides under mma) -----------
        float4 cpre[4];
        #pragma unroll
        for (int ii = 0; ii < 4; ++ii) {
            int i = tid + ii * 256;
            int r = i >> 4, q = i & 15;
            int grow = row0 + r; if (grow >= N) grow = N - 1;
            cpre[ii] = ((const float4*)c)[(size_t)grow * 32 + cH * 16 + q];
        }
        // ---- Stage next slab's A into the other buffer --------------------
        if (sl + 148 < nSlab)
            stageA(sm + (buf ? GA_A0 : GA_A1), x4, h4, (sl + 148) * 64, N, tid);

        // ---- Barrier-free mma mainloop ------------------------------------
        const uint32_t aBase = buf ? aB1 : aB0;
        float acc[2][8][4];
        #pragma unroll
        for (int m = 0; m < 2; ++m)
            #pragma unroll
            for (int t = 0; t < 8; ++t)
                #pragma unroll
                for (int e = 0; e < 4; ++e) acc[m][t][e] = 0.f;

        #pragma unroll
        for (int s = 0; s < 9; ++s) {
            uint32_t a[2][4];
            ldm4(a[0][0], a[0][1], a[0][2], a[0][3], aBase + s * 32);
            ldm4(a[1][0], a[1][1], a[1][2], a[1][3], aBase + s * 32 + 16 * 304);
            const uint32_t* bb = sBu + ((s * 2 + wgl) * 16 + t0) * 64 + lane * 2;
            #pragma unroll
            for (int t = 0; t < 8; ++t) {
                uint32_t b0 = bb[t * 64], b1 = bb[t * 64 + 1];
                mma16(acc[0][t][0], acc[0][t][1], acc[0][t][2], acc[0][t][3],
                      a[0][0], a[0][1], a[0][2], a[0][3], b0, b1);
                mma16(acc[1][t][0], acc[1][t][1], acc[1][t][2], acc[1][t][3],
                      a[1][0], a[1][1], a[1][2], a[1][3], b0, b1);
            }
        }
        __syncthreads();   // mma done reading A[buf] -> reuse as epilogue buf

        float* U = (float*)(sm + (buf ? GA_A1 : GA_A0));

        // ---- Stage c into U ------------------------------------------------
        #pragma unroll
        for (int ii = 0; ii < 4; ++ii) {
            int i = tid + ii * 256;
            int r = i >> 4, q = i & 15;
            *(float4*)&U[r * 68 + q * 4] = cpre[ii];
        }
        __syncthreads();

        // ---- LSTM cell math; cn written in place over c --------------------
        float hnreg[16];
        #pragma unroll
        for (int m = 0; m < 2; ++m) {
            const int rbase = warpM * 32 + m * 16 + g4;
            #pragma unroll
            for (int t = 0; t < 8; ++t) {
                float c0 = acc[m][t][0], c1 = acc[m][t][1];
                float c2 = acc[m][t][2], c3 = acc[m][t][3];
                float o0 = __shfl_xor_sync(0xffffffffu, c0, 1);
                float o1 = __shfl_xor_sync(0xffffffffu, c1, 1);
                float o2 = __shfl_xor_sync(0xffffffffu, c2, 1);
                float o3 = __shfl_xor_sync(0xffffffffu, c3, 1);
                int jl = wgl * 32 + (t0 + t) * 2 + (tg >> 1);
                int odd = lane & 1;
                int r = odd ? rbase + 8 : rbase;
                float gi = odd ? o2 : c0;
                float gf = odd ? o3 : c1;
                float gc = odd ? c2 : o0;
                float go = odd ? c3 : o1;
                float co = U[r * 68 + jl];
                float pi = gi + sBias[jl]       + sPeep[jl] * co;
                float pf = gf + sBias[64 + jl]  + sPeep[64 + jl] * co;
                float pc = gc + sBias[128 + jl];
                float po = go + sBias[192 + jl];
                float iv = sigm(pi), fv = sigm(pf), tv = tanhv(pc);
                float cn = fv * co + iv * tv;
                float ov = sigm(po + sPeep[128 + jl] * cn);
                U[r * 68 + jl] = cn;              // same owner as the read
                hnreg[m * 8 + t] = ov * tanhv(cn);
            }
        }
        __syncthreads();

        // ---- Coalesced c_new stores ---------------------------------------
        #pragma unroll
        for (int ii = 0; ii < 4; ++ii) {
            int i = tid + ii * 256;
            int r = i >> 4, q = i & 15;
            int grow = row0 + r;
            if (grow < N)
                ((float4*)outc)[(size_t)grow * 32 + cH * 16 + q] =
                    *(float4*)&U[r * 68 + q * 4];
        }
        __syncthreads();

        // ---- h_new into U, then coalesced stores --------------------------
        #pragma unroll
        for (int m = 0; m < 2; ++m) {
            const int rbase = warpM * 32 + m * 16 + g4;
            #pragma unroll
            for (int t = 0; t < 8; ++t) {
                int jl = wgl * 32 + (t0 + t) * 2 + (tg >> 1);
                int r = (lane & 1) ? rbase + 8 : rbase;
                U[r * 68 + jl] = hnreg[m * 8 + t];
            }
        }
        __syncthreads();
        #pragma unroll
        for (int ii = 0; ii < 4; ++ii) {
            int i = tid + ii * 256;
            int r = i >> 4, q = i & 15;
            int grow = row0 + r;
            if (grow < N)
                ((float4*)outh)[(size_t)grow * 32 + cH * 16 + q] =
                    *(float4*)&U[r * 68 + q * 4];
        }
        __syncthreads();   // U free before next iteration's staging into it
    }
}

// ---------------------------------------------------------------------------
// MLP head on fp16 mma (round-7 validated).
// ---------------------------------------------------------------------------
#define ML_A1   0
#define ML_W1F  17408
#define ML_W2F  33792
#define ML_A2   41984
#define ML_L2   51200
#define ML_SB   68608
#define MLP_SMEM_BYTES 69376

__global__ __launch_bounds__(256)
void mlp_mma(const float* __restrict__ hsrc,
             const float* __restrict__ b1, const float* __restrict__ b2,
             const float* __restrict__ w3, const float* __restrict__ b3,
             float* __restrict__ out, int N)
{
    extern __shared__ char sm[];
    char* sA1 = sm + ML_A1;
    const uint32_t* sW1u = (const uint32_t*)(sm + ML_W1F);
    const uint32_t* sW2u = (const uint32_t*)(sm + ML_W2F);
    char* sA2 = sm + ML_A2;
    float* sL2 = (float*)(sm + ML_L2);
    float* sB1 = (float*)(sm + ML_SB);
    float* sB2 = sB1 + 64;
    float* sW3 = sB1 + 128;

    const int tid   = threadIdx.x;
    const int lane  = tid & 31;
    const int wid   = tid >> 5;
    const int warpM = wid >> 2;
    const int warpN = wid & 3;
    const int g4    = lane >> 2;
    const int tg    = lane & 3;
    const int row0  = blockIdx.x * 64;

    #pragma unroll
    for (int ii = 0; ii < 4; ++ii) {
        int i = tid + ii * 256;
        int row = i >> 4, ch = i & 15;
        int grow = row0 + row; if (grow >= N) grow = N - 1;
        const float4* p = (const float4*)&hsrc[(size_t)grow * 128 + ch * 8];
        float4 v0 = p[0], v1 = p[1];
        v0.x = fmaxf(v0.x, 0.f); v0.y = fmaxf(v0.y, 0.f);
        v0.z = fmaxf(v0.z, 0.f); v0.w = fmaxf(v0.w, 0.f);
        v1.x = fmaxf(v1.x, 0.f); v1.y = fmaxf(v1.y, 0.f);
        v1.z = fmaxf(v1.z, 0.f); v1.w = fmaxf(v1.w, 0.f);
        uint4 o;
        o.x = f2h2(v0.x, v0.y); o.y = f2h2(v0.z, v0.w);
        o.z = f2h2(v1.x, v1.y); o.w = f2h2(v1.z, v1.w);
        *(uint4*)(sA1 + row * 272 + ch * 16) = o;
    }
    {
        const uint4* s1 = (const uint4*)g_W1f;
        uint4* d1 = (uint4*)(sm + ML_W1F);
        #pragma unroll
        for (int ii = 0; ii < 4; ++ii) d1[tid + ii * 256] = s1[tid + ii * 256];
        const uint4* s2 = (const uint4*)g_W2f;
        uint4* d2 = (uint4*)(sm + ML_W2F);
        #pragma unroll
        for (int ii = 0; ii < 2; ++ii) d2[tid + ii * 256] = s2[tid + ii * 256];
    }
    if (tid < 64) { sB1[tid] = b1[tid]; sB2[tid] = b2[tid]; sW3[tid] = w3[tid]; }
    __syncthreads();

    const int lrow = lane & 15;
    const int lkof = (lane >> 4) * 8;

    {
        const uint32_t aB = s2u(sA1) + (uint32_t)(warpM * 32 + lrow) * 272 + lkof * 2;
        float acc[2][2][4];
        #pragma unroll
        for (int m = 0; m < 2; ++m)
            #pragma unroll
            for (int t = 0; t < 2; ++t)
                #pragma unroll
                for (int e = 0; e < 4; ++e) acc[m][t][e] = 0.f;
        #pragma unroll
        for (int s = 0; s < 8; ++s) {
            uint32_t a[2][4];
            ldm4(a[0][0], a[0][1], a[0][2], a[0][3], aB + s * 32);
            ldm4(a[1][0], a[1][1], a[1][2], a[1][3], aB + s * 32 + 16 * 272);
            #pragma unroll
            for (int t = 0; t < 2; ++t) {
                const uint32_t* bb = sW1u + ((s * 8 + warpN * 2 + t) * 32 + lane) * 2;
                uint32_t b0 = bb[0], b1v = bb[1];
                mma16(acc[0][t][0], acc[0][t][1], acc[0][t][2], acc[0][t][3],
                      a[0][0], a[0][1], a[0][2], a[0][3], b0, b1v);
                mma16(acc[1][t][0], acc[1][t][1], acc[1][t][2], acc[1][t][3],
                      a[1][0], a[1][1], a[1][2], a[1][3], b0, b1v);
            }
        }
        #pragma unroll
        for (int t = 0; t < 2; ++t) {
            int col = (warpN * 2 + t) * 8 + tg * 2;
            float ba = sB1[col], bb2 = sB1[col + 1];
            #pragma unroll
            for (int m = 0; m < 2; ++m) {
                int r = warpM * 32 + m * 16 + g4;
                float v0 = fmaxf(acc[m][t][0] + ba, 0.f);
                float v1 = fmaxf(acc[m][t][1] + bb2, 0.f);
                float v2 = fmaxf(acc[m][t][2] + ba, 0.f);
                float v3 = fmaxf(acc[m][t][3] + bb2, 0.f);
                *(uint32_t*)(sA2 + r * 144 + col * 2) = f2h2(v0, v1);
                *(uint32_t*)(sA2 + (r + 8) * 144 + col * 2) = f2h2(v2, v3);
            }
        }
    }
    __syncthreads();

    {
        const uint32_t aB = s2u(sA2) + (uint32_t)(warpM * 32 + lrow) * 144 + lkof * 2;
        float acc[2][2][4];
        #pragma unroll
        for (int m = 0; m < 2; ++m)
            #pragma unroll
            for (int t = 0; t < 2; ++t)
                #pragma unroll
                for (int e = 0; e < 4; ++e) acc[m][t][e] = 0.f;
        #pragma unroll
        for (int s = 0; s < 4; ++s) {
            uint32_t a[2][4];
            ldm4(a[0][0], a[0][1], a[0][2], a[0][3], aB + s * 32);
            ldm4(a[1][0], a[1][1], a[1][2], a[1][3], aB + s * 32 + 16 * 144);
            #pragma unroll
            for (int t = 0; t < 2; ++t) {
                const uint32_t* bb = sW2u + ((s * 8 + warpN * 2 + t) * 32 + lane) * 2;
                uint32_t b0 = bb[0], b1v = bb[1];
                mma16(acc[0][t][0], acc[0][t][1], acc[0][t][2], acc[0][t][3],
                      a[0][0], a[0][1], a[0][2], a[0][3], b0, b1v);
                mma16(acc[1][t][0], acc[1][t][1], acc[1][t][2], acc[1][t][3],
                      a[1][0], a[1][1], a[1][2], a[1][3], b0, b1v);
            }
        }
        #pragma unroll
        for (int t = 0; t < 2; ++t) {
            int col = (warpN * 2 + t) * 8 + tg * 2;
            float ba = sB2[col], bb2 = sB2[col + 1];
            #pragma unroll
            for (int m = 0; m < 2; ++m) {
                int r = warpM * 32 + m * 16 + g4;
                *(float2*)&sL2[r * 68 + col] =
                    make_float2(fmaxf(acc[m][t][0] + ba, 0.f),
                                fmaxf(acc[m][t][1] + bb2, 0.f));
                *(float2*)&sL2[(r + 8) * 68 + col] =
                    make_float2(fmaxf(acc[m][t][2] + ba, 0.f),
                                fmaxf(acc[m][t][3] + bb2, 0.f));
            }
        }
    }
    __syncthreads();

    if (tid < 64) {
        int grow = row0 + tid;
        if (grow < N) {
            float a = b3[0];
            #pragma unroll
            for (int k = 0; k < 64; ++k) a += sL2[tid * 68 + k] * sW3[k];
            out[grow] = a;
        }
    }
}

// ---------------------------------------------------------------------------
extern "C" void kernel_launch(void* const* d_in, const int* in_sizes, int n_in,
                              void* d_out, int out_size)
{
    const float* x   = (const float*)d_in[0];
    const float* h   = (const float*)d_in[3];
    const float* c   = (const float*)d_in[4];
    const float* Wi  = (const float*)d_in[5];
    const float* Wf  = (const float*)d_in[6];
    const float* Wc  = (const float*)d_in[7];
    const float* Wo  = (const float*)d_in[8];
    const float* Ci  = (const float*)d_in[9];
    const float* Cf  = (const float*)d_in[10];
    const float* Cc  = (const float*)d_in[11];
    const float* Co  = (const float*)d_in[12];
    const float* cbi = (const float*)d_in[13];
    const float* cbf = (const float*)d_in[14];
    const float* cbc = (const float*)d_in[15];
    const float* cbo = (const float*)d_in[16];
    const float* wci = (const float*)d_in[17];
    const float* wcf = (const float*)d_in[18];
    const float* wco = (const float*)d_in[19];
    const float* bi  = (const float*)d_in[20];
    const float* bf  = (const float*)d_in[21];
    const float* bc  = (const float*)d_in[22];
    const float* bo  = (const float*)d_in[23];
    const float* w1  = (const float*)d_in[24];
    const float* b1  = (const float*)d_in[25];
    const float* w2  = (const float*)d_in[26];
    const float* b2  = (const float*)d_in[27];
    const float* w3  = (const float*)d_in[28];
    const float* b3  = (const float*)d_in[29];

    const int N = in_sizes[3] / 128;
    const int nSlab = (N + 63) / 64;

    float* out  = (float*)d_out;
    float* outh = out + N;
    float* outc = outh + (size_t)N * 128;

    pack_kernel<<<(74240 + 8192 + 4096 + 255) / 256, 256>>>(
        Wi, Wf, Wc, Wo, Ci, Cf, Cc, Co,
        cbi, cbf, cbc, cbo, bi, bf, bc, bo, w1, w2);

    cudaFuncSetAttribute(gates_mma,
                         cudaFuncAttributeMaxDynamicSharedMemorySize,
                         GATES_SMEM_BYTES);
    gates_mma<<<296, 256, GATES_SMEM_BYTES>>>(
        x, h, c, wci, wcf, wco, outh, outc, N, nSlab);

    cudaFuncSetAttribute(mlp_mma,
                         cudaFuncAttributeMaxDynamicSharedMemorySize,
                         MLP_SMEM_BYTES);
    mlp_mma<<<(N + 63) / 64, 256, MLP_SMEM_BYTES>>>(
        outh, b1, b2, w3, b3, out, N);
}